// round 11
// baseline (speedup 1.0000x reference)
#include <cuda_runtime.h>
#include <cuda_fp16.h>
#include <stdint.h>

#define BB 2
#define NH 8
#define TT 192
#define HD 64
#define CC 512
#define BH 16            // BB*NH
#define NTILE 6          // TT/32
#define NTRI 56          // # (ti,tj,kc) triples, kc<=tj<=ti<6
#define NSLAB 21         // # (tj,kc) pairs
#define QPRE 0.18033688f // 0.125 * log2(e): exp(S/8) = exp2(S*QPRE)
#define XN (BB*TT*CC)    // 196608
#define WN (CC*CC)       // 262144

// triple table: ti | tj<<3 | kc<<6 | slab<<9, slab = tj*(tj+1)/2 + kc
#define E(ti,tj,kc) ((ti)|((tj)<<3)|((kc)<<6)|(((tj)*((tj)+1)/2+(kc))<<9))
__device__ __constant__ int c_map[NTRI] = {
    E(0,0,0),
    E(1,0,0), E(1,1,0), E(1,1,1),
    E(2,0,0), E(2,1,0), E(2,1,1), E(2,2,0), E(2,2,1), E(2,2,2),
    E(3,0,0), E(3,1,0), E(3,1,1), E(3,2,0), E(3,2,1), E(3,2,2),
    E(3,3,0), E(3,3,1), E(3,3,2), E(3,3,3),
    E(4,0,0), E(4,1,0), E(4,1,1), E(4,2,0), E(4,2,1), E(4,2,2),
    E(4,3,0), E(4,3,1), E(4,3,2), E(4,3,3),
    E(4,4,0), E(4,4,1), E(4,4,2), E(4,4,3), E(4,4,4),
    E(5,0,0), E(5,1,0), E(5,1,1), E(5,2,0), E(5,2,1), E(5,2,2),
    E(5,3,0), E(5,3,1), E(5,3,2), E(5,3,3),
    E(5,4,0), E(5,4,1), E(5,4,2), E(5,4,3), E(5,4,4),
    E(5,5,0), E(5,5,1), E(5,5,2), E(5,5,3), E(5,5,4), E(5,5,5)
};
__device__ __constant__ int c_slab_tj[NSLAB] =
    {0, 1,1, 2,2,2, 3,3,3,3, 4,4,4,4,4, 5,5,5,5,5,5};

// persistent device scratch (no allocations allowed)
__device__ __align__(16) float    g_q [BH*TT*HD];
__device__ __align__(16) float    g_k1[BH*TT*HD];
__device__ __align__(16) float    g_k2[BH*TT*HD];
__device__ __align__(16) float    g_Np[NSLAB*BH*TT*HD];  // 21 slabs
__device__ __align__(16) float    g_Zp[BH*NTRI];
__device__ __align__(16) unsigned g_xs[XN];        // x packed split-fp16
__device__ __align__(16) unsigned g_Ws[4][WN];     // W0,W1,W2,Wp packed
__device__ __align__(16) unsigned g_ys[XN];        // normalized y packed
__device__ __align__(16) float    g_outp[2][XN];   // out K-split partials

// ---------------------------------------------------------------------------
// HMMA helpers
__device__ __forceinline__ unsigned int pkh2(float a, float b)
{
    __half2 h = __floats2half2_rn(a, b);
    return *reinterpret_cast<unsigned int*>(&h);
}

__device__ __forceinline__ void mma16816(float* d, const unsigned int* a, const unsigned int* b)
{
    asm volatile(
        "mma.sync.aligned.m16n8k16.row.col.f32.f16.f16.f32 "
        "{%0,%1,%2,%3}, {%4,%5,%6,%7}, {%8,%9}, {%0,%1,%2,%3};\n"
        : "+f"(d[0]), "+f"(d[1]), "+f"(d[2]), "+f"(d[3])
        : "r"(a[0]), "r"(a[1]), "r"(a[2]), "r"(a[3]), "r"(b[0]), "r"(b[1]));
}

__device__ __forceinline__ void ldsm_x2_trans(unsigned& r0, unsigned& r1, unsigned addr)
{
    asm volatile("ldmatrix.sync.aligned.m8n8.x2.trans.shared.b16 {%0,%1}, [%2];"
        : "=r"(r0), "=r"(r1) : "r"(addr));
}

__device__ __forceinline__ void ldsm_x4(unsigned& r0, unsigned& r1, unsigned& r2,
                                        unsigned& r3, unsigned addr)
{
    asm volatile("ldmatrix.sync.aligned.m8n8.x4.shared.b16 {%0,%1,%2,%3}, [%4];"
        : "=r"(r0), "=r"(r1), "=r"(r2), "=r"(r3) : "r"(addr));
}

__device__ __forceinline__ unsigned su32(const void* p)
{
    return (unsigned)__cvta_generic_to_shared(p);
}

// bare MUFU exp2 (exp2f without fast-math is a softfloat routine)
__device__ __forceinline__ float ex2(float x)
{
    float y;
    asm("ex2.approx.ftz.f32 %0, %1;" : "=f"(y) : "f"(x));
    return y;
}

// pack value as (hi fp16) | (lo fp16 << 16); hi+lo ~ 22-bit mantissa of f
__device__ __forceinline__ unsigned int splitpack(float f)
{
    __half h = __float2half_rn(f);
    __half l = __float2half_rn(f - __half2float(h));
    return (unsigned int)__half_as_ushort(h) | ((unsigned int)__half_as_ushort(l) << 16);
}

// ---------------------------------------------------------------------------
// convert x + W0..W2 to packed split-fp16 (float4-vectorized)
__global__ __launch_bounds__(256)
void cvt_main(const float* __restrict__ x,  const float* __restrict__ W0,
              const float* __restrict__ W1, const float* __restrict__ W2)
{
    int i4 = (blockIdx.x * 256 + threadIdx.x) * 4;   // 960 blocks: XN + 3*WN
    const float* src;
    unsigned*    dst;
    if (i4 < XN) {
        src = x + i4;
        dst = g_xs + i4;
    } else {
        int o = i4 - XN;
        int r = o >> 18;          // WN = 2^18
        o &= (WN - 1);
        src = (r == 0 ? W0 : r == 1 ? W1 : W2) + o;
        dst = g_Ws[r] + o;
    }
    float4 v = *(const float4*)src;
    uint4 u;
    u.x = splitpack(v.x); u.y = splitpack(v.y);
    u.z = splitpack(v.z); u.w = splitpack(v.w);
    *(uint4*)dst = u;
}

// convert Wp (separate launch — keeps attn in the ncu-profiled slot #4)
__global__ __launch_bounds__(256)
void cvt_wp(const float* __restrict__ Wp)
{
    int i4 = (blockIdx.x * 256 + threadIdx.x) * 4;   // 256 blocks: WN
    float4 v = *(const float4*)(Wp + i4);
    uint4 u;
    u.x = splitpack(v.x); u.y = splitpack(v.y);
    u.z = splitpack(v.z); u.w = splitpack(v.w);
    *(uint4*)&g_Ws[3][i4] = u;
}

// ---------------------------------------------------------------------------
// split-fp16 GEMM core on pre-packed operands (row stride 68 = 16B-aligned rows)
__device__ __forceinline__ void gemm64_core(
    const unsigned* __restrict__ A, const unsigned* __restrict__ B,
    int row0, int col0, int kb, int ke, float (&acc)[2][2][4],
    unsigned (*sA)[68], unsigned (*sB)[68])
{
    const int tid = threadIdx.x;
    const int w  = tid >> 5, l = tid & 31;
    const int wm = w >> 2, wn = w & 3;
    const int g  = l >> 2, c2 = (l & 3) << 1;
    const int lr = tid >> 2, lc0 = (tid & 3) << 4;

    for (int kc = kb; kc < ke; kc += 64) {
        const unsigned* ap = A + (row0 + lr)*CC + kc + lc0;
        const unsigned* bp = B + (col0 + lr)*CC + kc + lc0;
        #pragma unroll
        for (int v = 0; v < 4; ++v) {
            *(uint4*)&sA[lr][lc0 + v*4] = *(const uint4*)(ap + v*4);
            *(uint4*)&sB[lr][lc0 + v*4] = *(const uint4*)(bp + v*4);
        }
        __syncthreads();
        #pragma unroll
        for (int ks = 0; ks < 4; ++ks) {
            const int k0 = ks*16 + c2;
            unsigned ahi[2][4], alo[2][4];
            #pragma unroll
            for (int mt = 0; mt < 2; ++mt) {
                const int r = wm*32 + mt*16 + g;
                uint2 p0 = *(const uint2*)&sA[r    ][k0    ];
                uint2 p1 = *(const uint2*)&sA[r + 8][k0    ];
                uint2 p2 = *(const uint2*)&sA[r    ][k0 + 8];
                uint2 p3 = *(const uint2*)&sA[r + 8][k0 + 8];
                ahi[mt][0] = __byte_perm(p0.x, p0.y, 0x5410);
                alo[mt][0] = __byte_perm(p0.x, p0.y, 0x7632);
                ahi[mt][1] = __byte_perm(p1.x, p1.y, 0x5410);
                alo[mt][1] = __byte_perm(p1.x, p1.y, 0x7632);
                ahi[mt][2] = __byte_perm(p2.x, p2.y, 0x5410);
                alo[mt][2] = __byte_perm(p2.x, p2.y, 0x7632);
                ahi[mt][3] = __byte_perm(p3.x, p3.y, 0x5410);
                alo[mt][3] = __byte_perm(p3.x, p3.y, 0x7632);
            }
            #pragma unroll
            for (int nt = 0; nt < 2; ++nt) {
                const int n = wn*16 + nt*8 + g;
                uint2 q0 = *(const uint2*)&sB[n][k0    ];
                uint2 q1 = *(const uint2*)&sB[n][k0 + 8];
                unsigned bhi[2], blo[2];
                bhi[0] = __byte_perm(q0.x, q0.y, 0x5410);
                blo[0] = __byte_perm(q0.x, q0.y, 0x7632);
                bhi[1] = __byte_perm(q1.x, q1.y, 0x5410);
                blo[1] = __byte_perm(q1.x, q1.y, 0x7632);
                #pragma unroll
                for (int mt = 0; mt < 2; ++mt) {
                    mma16816(acc[mt][nt], ahi[mt], bhi);
                    mma16816(acc[mt][nt], ahi[mt], blo);
                    mma16816(acc[mt][nt], alo[mt], bhi);
                }
            }
        }
        __syncthreads();
    }
}

// ---------------------------------------------------------------------------
// projections: q = x@W0^T, k1 = x@W1^T, k2 = x@W2^T, stored [bh][t][d]
__global__ __launch_bounds__(256)
void proj_kernel()
{
    __shared__ __align__(16) unsigned sA[64][68];
    __shared__ __align__(16) unsigned sB[64][68];
    float* dst = (blockIdx.z == 0) ? g_q : (blockIdx.z == 1) ? g_k1 : g_k2;
    const int row0 = blockIdx.y * 64, col0 = blockIdx.x * 64;
    float acc[2][2][4];
    #pragma unroll
    for (int a = 0; a < 2; ++a)
        #pragma unroll
        for (int b = 0; b < 2; ++b)
            #pragma unroll
            for (int c = 0; c < 4; ++c) acc[a][b][c] = 0.f;
    gemm64_core(g_xs, g_Ws[blockIdx.z], row0, col0, 0, CC, acc, sA, sB);

    const int w = threadIdx.x >> 5, l = threadIdx.x & 31;
    const int wm = w >> 2, wn = w & 3;
    #pragma unroll
    for (int mt = 0; mt < 2; ++mt)
        #pragma unroll
        for (int nt = 0; nt < 2; ++nt) {
            const int col = col0 + wn*16 + nt*8 + ((l & 3) << 1);
            const int h = col >> 6, d = col & 63;
            #pragma unroll
            for (int rh = 0; rh < 2; ++rh) {
                const int row = row0 + wm*32 + mt*16 + (l >> 2) + rh*8;
                const int b = row / TT, t = row - b*TT;
                float2 v = make_float2(acc[mt][nt][rh*2], acc[mt][nt][rh*2 + 1]);
                *(float2*)&dst[((b*NH + h)*TT + t)*HD + d] = v;
            }
        }
}

// ---------------------------------------------------------------------------
// one 32-token k-chunk: score MMA + ex2 + j-fold -> Qtab row (no PV here).
// kg0: global k base of this chunk; smem k2s holds the chunk at local rows 0..31.
template<bool MJ, bool MK>
__device__ __forceinline__ void do_chunk(
    int kg0, int ig, int il, int j0, int g, int q2, int lane, unsigned bbase,
    const unsigned (&afr)[2][4][4], __half (*Qtab)[40], float& zacc)
{
    #pragma unroll
    for (int nt = 0; nt < 4; ++nt) {
        if (MJ && MK && (kg0 + nt*8) > ig) continue;  // fully-masked token group
        // B fragments via 2x ldmatrix.x4 (8 tiles: 4 ks x 2 k-halves)
        unsigned bfr[4][2];
        {
            unsigned a0 = bbase + nt*(8*144);          // +8 local token rows
            ldsm_x4(bfr[0][0], bfr[0][1], bfr[1][0], bfr[1][1], a0);
            ldsm_x4(bfr[2][0], bfr[2][1], bfr[3][0], bfr[3][1], a0 + 64);
        }
        float Qf0 = 0.f, Qf1 = 0.f;
        #pragma unroll
        for (int mt = 0; mt < 2; ++mt) {
            if (MJ && (j0 + mt*16) > ig) continue;    // whole 16-row group above i
            float acc[4] = {0.f, 0.f, 0.f, 0.f};
            #pragma unroll
            for (int ks = 0; ks < 4; ++ks) mma16816(acc, afr[mt][ks], bfr[ks]);
            const int jlo = j0 + mt*16 + g, jhi = jlo + 8;
            const int k0  = kg0 + nt*8 + q2, k1 = k0 + 1;
            bool v0 = (!MJ || jlo <= ig) && (!MK || k0 <= jlo);
            bool v1 = (!MJ || jlo <= ig) && (!MK || k1 <= jlo);
            bool v2 = (!MJ || jhi <= ig) && (!MK || k0 <= jhi);
            bool v3 = (!MJ || jhi <= ig) && (!MK || k1 <= jhi);
            float p0 = v0 ? ex2(acc[0]) : 0.f;        // scale pre-folded into q
            float p1 = v1 ? ex2(acc[1]) : 0.f;
            float p2 = v2 ? ex2(acc[2]) : 0.f;
            float p3 = v3 ? ex2(acc[3]) : 0.f;
            Qf0 += p0 + p2;
            Qf1 += p1 + p3;
        }
        // fold across the 8 j row-groups (lanes differing in bits 2..4)
        #pragma unroll
        for (int m = 4; m <= 16; m <<= 1) {
            Qf0 += __shfl_xor_sync(0xffffffffu, Qf0, m);
            Qf1 += __shfl_xor_sync(0xffffffffu, Qf1, m);
        }
        zacc += (Qf0 + Qf1) * 0.125f;                 // 8-lane replication
        unsigned qp = pkh2(Qf0, Qf1);
        if (lane < 4)                                  // lanes 0..3 cover 8 tokens
            *(unsigned*)&Qtab[il][nt*8 + (lane << 1)] = qp;
    }
}

// ---------------------------------------------------------------------------
// uniform-work attention: block = (bh, ti, tj, kc) triple; 896 blocks.
// scores (HMMA) + ex2 + j-fold -> Qtab; PV = one K=32 block GEMM.
__global__ __launch_bounds__(256, 3)
void attn_kernel()
{
    __shared__ __align__(16) __half k2s[32][72];
    __shared__ __align__(16) float  qs [32][65];
    __shared__ __align__(16) float  k1s[32][65];
    __shared__ __align__(16) __half Qtab[32][40];
    __shared__ float zred[8];

    const int bh  = blockIdx.x & 15;
    const int m   = c_map[blockIdx.x >> 4];
    const int ti  = m & 7, tj = (m >> 3) & 7, kc = (m >> 6) & 7, slab = m >> 9;
    const int i0 = ti * 32, j0 = tj * 32;
    const int tid  = threadIdx.x;
    const int w    = tid >> 5, lane = tid & 31;
    const int g    = lane >> 2, q2 = (lane & 3) << 1;
    const bool diag = (ti == tj);
    const bool mk   = (kc == tj);
    const int kg0 = kc * 32;

    // ldmatrix lane base (local chunk rows 0..31)
    const unsigned bmat0 = su32(&k2s[0][0]) + (lane & 7)*144 + (lane >> 3)*16;

    // load q (prescaled by QPRE) / k1 fp32 (float4); k2 chunk fp16; zero Qtab
    {
        const float* qg  = g_q  + (bh*TT + i0)*HD;
        const float* k1g = g_k1 + (bh*TT + j0)*HD;
        const float* k2g = g_k2 + (bh*TT + kg0)*HD;
        for (int l = tid; l < 512; l += 256) {
            int r = l >> 4, c4 = (l & 15) << 2;
            float4 vq = *(const float4*)(qg + r*HD + c4);
            qs[r][c4]   = vq.x * QPRE; qs[r][c4+1] = vq.y * QPRE;
            qs[r][c4+2] = vq.z * QPRE; qs[r][c4+3] = vq.w * QPRE;
            float4 vk = *(const float4*)(k1g + r*HD + c4);
            k1s[r][c4]   = vk.x; k1s[r][c4+1] = vk.y;
            k1s[r][c4+2] = vk.z; k1s[r][c4+3] = vk.w;
            float4 v2 = *(const float4*)(k2g + r*HD + c4);
            *(__half2*)&k2s[r][c4]     = __floats2half2_rn(v2.x, v2.y);
            *(__half2*)&k2s[r][c4 + 2] = __floats2half2_rn(v2.z, v2.w);
        }
        for (int l = tid; l < 640; l += 256)           // 32 x 40 halves = 640 uint
            ((unsigned*)Qtab)[l] = 0u;
    }
    __syncthreads();

    float zacc = 0.f;

    for (int isub = 0; isub < 4; ++isub) {
        const int il = isub*8 + w;
        const int ig = i0 + il;

        // A fragments: W[j,d] = q[i,d]*k1[j,d] (fp16)
        unsigned afr[2][4][4];
        #pragma unroll
        for (int mt = 0; mt < 2; ++mt) {
            const int jlo = mt*16 + g, jhi = jlo + 8;
            #pragma unroll
            for (int ks = 0; ks < 4; ++ks) {
                const int d0 = ks*16 + q2;
                float qa = qs[il][d0],   qb = qs[il][d0+1];
                float qc = qs[il][d0+8], qd = qs[il][d0+9];
                afr[mt][ks][0] = pkh2(qa*k1s[jlo][d0],   qb*k1s[jlo][d0+1]);
                afr[mt][ks][1] = pkh2(qa*k1s[jhi][d0],   qb*k1s[jhi][d0+1]);
                afr[mt][ks][2] = pkh2(qc*k1s[jlo][d0+8], qd*k1s[jlo][d0+9]);
                afr[mt][ks][3] = pkh2(qc*k1s[jhi][d0+8], qd*k1s[jhi][d0+9]);
            }
        }

        if (diag) {
            if (mk) do_chunk<true ,true >(kg0, ig, il, j0, g, q2, lane, bmat0, afr, Qtab, zacc);
            else    do_chunk<true ,false>(kg0, ig, il, j0, g, q2, lane, bmat0, afr, Qtab, zacc);
        } else {
            if (mk) do_chunk<false,true >(kg0, ig, il, j0, g, q2, lane, bmat0, afr, Qtab, zacc);
            else    do_chunk<false,false>(kg0, ig, il, j0, g, q2, lane, bmat0, afr, Qtab, zacc);
        }
    }
    __syncthreads();

    // ---- PV: Np[32i, 64d] = Qtab[32i, 32k] @ k2[32k, 64d] (one block GEMM) ----
    {
        const int gi = w & 1;           // i-group (16 rows)
        const int dt = w >> 1;          // d-tiles dt*8 and dt*8+32
        const int r0 = gi*16 + g;
        float pacc[2][4];
        #pragma unroll
        for (int t2 = 0; t2 < 2; ++t2)
            pacc[t2][0] = pacc[t2][1] = pacc[t2][2] = pacc[t2][3] = 0.f;

        #pragma unroll
        for (int ks = 0; ks < 32; ks += 16) {
            unsigned afrag[4];
            afrag[0] = *(const unsigned*)&Qtab[r0    ][ks + q2];
            afrag[1] = *(const unsigned*)&Qtab[r0 + 8][ks + q2];
            afrag[2] = *(const unsigned*)&Qtab[r0    ][ks + 8 + q2];
            afrag[3] = *(const unsigned*)&Qtab[r0 + 8][ks + 8 + q2];
            #pragma unroll
            for (int t2 = 0; t2 < 2; ++t2) {
                const int d0 = dt*8 + t2*32;
                unsigned b0, b1;
                ldsm_x2_trans(b0, b1, su32(&k2s[ks + (lane & 15)][d0]));
                unsigned bfrag[2] = {b0, b1};
                mma16816(pacc[t2], afrag, bfrag);
            }
        }
        float* np = g_Np + ((slab*BH + bh)*TT + i0)*HD;
        #pragma unroll
        for (int t2 = 0; t2 < 2; ++t2) {
            const int d0 = dt*8 + t2*32 + q2;
            *(float2*)&np[(r0    )*HD + d0] = make_float2(pacc[t2][0], pacc[t2][1]);
            *(float2*)&np[(r0 + 8)*HD + d0] = make_float2(pacc[t2][2], pacc[t2][3]);
        }
    }

    // Z partial: block-reduce
    #pragma unroll
    for (int m2 = 16; m2 >= 1; m2 >>= 1)
        zacc += __shfl_xor_sync(0xffffffffu, zacc, m2);
    if (lane == 0) zred[w] = zacc;
    __syncthreads();
    if (tid == 0) {
        float z = 0.f;
        #pragma unroll
        for (int ww = 0; ww < 8; ++ww) z += zred[ww];
        g_Zp[bh*NTRI + (blockIdx.x >> 4)] = z;
    }
}

// ---------------------------------------------------------------------------
// y = (sum of valid slab partials)/Z, written PACKED split-fp16 for out GEMM
__global__ __launch_bounds__(256)
void finalize_y()
{
    __shared__ float invZ[BH];
    const int tid = threadIdx.x;
    if (tid < BH) {
        float z = 0.f;
        for (int pp = 0; pp < NTRI; ++pp) z += g_Zp[tid*NTRI + pp];
        invZ[tid] = 1.f / z;
    }
    __syncthreads();
    int e  = blockIdx.x * 256 + tid;    // < XN/4 = 49152
    int c4 = e & 127;
    int r  = e >> 7;
    int b = r / TT, t = r - b*TT;
    int h = c4 >> 4, d4 = c4 & 15;
    int bh = b*NH + h;
    float4 acc = make_float4(0.f, 0.f, 0.f, 0.f);
    const int timax = t >> 5;
    #pragma unroll
    for (int s = 0; s < NSLAB; ++s) {      // predicated -> MLP 21
        if (c_slab_tj[s] <= timax) {
            float4 v = *(const float4*)&g_Np[((s*BH + bh)*TT + t)*HD + d4*4];
            acc.x += v.x; acc.y += v.y; acc.z += v.z; acc.w += v.w;
        }
    }
    float iz = invZ[bh];
    uint4 u;
    u.x = splitpack(acc.x * iz); u.y = splitpack(acc.y * iz);
    u.z = splitpack(acc.z * iz); u.w = splitpack(acc.w * iz);
    *(uint4*)&g_ys[r*CC + c4*4] = u;
}

// ---------------------------------------------------------------------------
// out partials: K-split halves of y @ Wp^T
__global__ __launch_bounds__(256)
void out_kernel()
{
    __shared__ __align__(16) unsigned sA[64][68];
    __shared__ __align__(16) unsigned sB[64][68];
    const int row0 = blockIdx.y * 64, col0 = blockIdx.x * 64;
    const int z = blockIdx.z;
    float acc[2][2][4];
    #pragma unroll
    for (int a = 0; a < 2; ++a)
        #pragma unroll
        for (int b = 0; b < 2; ++b)
            #pragma unroll
            for (int c = 0; c < 4; ++c) acc[a][b][c] = 0.f;
    gemm64_core(g_ys, g_Ws[3], row0, col0, z*(CC/2), (z+1)*(CC/2), acc, sA, sB);

    const int w = threadIdx.x >> 5, l = threadIdx.x & 31;
    const int wm = w >> 2, wn = w & 3;
    float* op = g_outp[z];
    #pragma unroll
    for (int mt = 0; mt < 2; ++mt)
        #pragma unroll
        for (int nt = 0; nt < 2; ++nt) {
            const int col = col0 + wn*16 + nt*8 + ((l & 3) << 1);
            #pragma unroll
            for (int rh = 0; rh < 2; ++rh) {
                const int row = row0 + wm*32 + mt*16 + (l >> 2) + rh*8;
                float2 v = make_float2(acc[mt][nt][rh*2], acc[mt][nt][rh*2 + 1]);
                *(float2*)&op[row*CC + col] = v;
            }
        }
}

// ---------------------------------------------------------------------------
__global__ __launch_bounds__(256)
void reduce_out(float* __restrict__ out)
{
    int e4 = (blockIdx.x * 256 + threadIdx.x) * 4;   // < XN
    float4 a = *(const float4*)&g_outp[0][e4];
    float4 b = *(const float4*)&g_outp[1][e4];
    float4 r = make_float4(a.x + b.x, a.y + b.y, a.z + b.z, a.w + b.w);
    *(float4*)&out[e4] = r;
}

// ---------------------------------------------------------------------------
extern "C" void kernel_launch(void* const* d_in, const int* in_sizes, int n_in,
                              void* d_out, int out_size)
{
    const float* x  = (const float*)d_in[0];
    const float* W0 = (const float*)d_in[1];
    const float* W1 = (const float*)d_in[2];
    const float* W2 = (const float*)d_in[3];
    const float* Wp = (const float*)d_in[4];
    float* out = (float*)d_out;

    cvt_main<<<(XN + 3*WN)/(256*4), 256>>>(x, W0, W1, W2);     // launch 1
    cvt_wp<<<WN/(256*4), 256>>>(Wp);                            // launch 2
    dim3 pg(CC/64, (BB*TT)/64, 3);
    proj_kernel<<<pg, 256>>>();                                 // launch 3
    attn_kernel<<<NTRI*BH, 256>>>();                            // launch 4 (profiled)
    finalize_y<<<(XN/4)/256, 256>>>();
    dim3 og(CC/64, (BB*TT)/64, 2);
    out_kernel<<<og, 256>>>();
    reduce_out<<<(XN/4)/256, 256>>>(out);
}

// round 12
// speedup vs baseline: 1.2257x; 1.2257x over previous
#include <cuda_runtime.h>
#include <cuda_fp16.h>
#include <stdint.h>

#define BB 2
#define NH 8
#define TT 192
#define HD 64
#define CC 512
#define BH 16            // BB*NH
#define NTILE 6          // TT/32
#define NJOB 27          // jobs per bh (heavy (ti,tj) split at kc midpoint)
#define NSLAB 9          // (tj, kc-half) slabs
#define QPRE 0.18033688f // 0.125 * log2(e): exp(S/8) = exp2(S*QPRE)
#define XN (BB*TT*CC)    // 196608
#define WN (CC*CC)       // 262144

// job encoding: ti | tj<<3 | kb<<6 | ke<<9 | slab<<13
#define EJ(ti,tj,kb,ke,slab) ((ti)|((tj)<<3)|((kb)<<6)|((ke)<<9)|((slab)<<13))
__device__ __constant__ int c_job[NJOB] = {
    // tj=0 (1 chunk)
    EJ(0,0,0,1,0), EJ(1,0,0,1,0), EJ(2,0,0,1,0), EJ(3,0,0,1,0), EJ(4,0,0,1,0), EJ(5,0,0,1,0),
    // tj=1 (2 chunks)
    EJ(1,1,0,2,1), EJ(2,1,0,2,1), EJ(3,1,0,2,1), EJ(4,1,0,2,1), EJ(5,1,0,2,1),
    // tj=2 (3 chunks)
    EJ(2,2,0,3,2), EJ(3,2,0,3,2), EJ(4,2,0,3,2), EJ(5,2,0,3,2),
    // tj=3 split 2+2
    EJ(3,3,0,2,3), EJ(3,3,2,4,4), EJ(4,3,0,2,3), EJ(4,3,2,4,4), EJ(5,3,0,2,3), EJ(5,3,2,4,4),
    // tj=4 split 2+3
    EJ(4,4,0,2,5), EJ(4,4,2,5,6), EJ(5,4,0,2,5), EJ(5,4,2,5,6),
    // tj=5 split 3+3
    EJ(5,5,0,3,7), EJ(5,5,3,6,8)
};
__device__ __constant__ int c_slab_tj[NSLAB] = {0,1,2,3,3,4,4,5,5};

// persistent device scratch (no allocations allowed)
__device__ __align__(16) float    g_q [BH*TT*HD];
__device__ __align__(16) float    g_k1[BH*TT*HD];
__device__ __align__(16) float    g_k2[BH*TT*HD];
__device__ __align__(16) float    g_Np[NSLAB*BH*TT*HD];  // 9 slabs
__device__ __align__(16) float    g_Zp[BH*NJOB];
__device__ __align__(16) unsigned g_xs[XN];        // x packed split-fp16
__device__ __align__(16) unsigned g_Ws[4][WN];     // W0,W1,W2,Wp packed
__device__ __align__(16) unsigned g_ys[XN];        // normalized y packed
__device__ __align__(16) float    g_outp[2][XN];   // out K-split partials

// ---------------------------------------------------------------------------
// HMMA helpers
__device__ __forceinline__ unsigned int pkh2(float a, float b)
{
    __half2 h = __floats2half2_rn(a, b);
    return *reinterpret_cast<unsigned int*>(&h);
}

__device__ __forceinline__ void mma16816(float* d, const unsigned int* a, const unsigned int* b)
{
    asm volatile(
        "mma.sync.aligned.m16n8k16.row.col.f32.f16.f16.f32 "
        "{%0,%1,%2,%3}, {%4,%5,%6,%7}, {%8,%9}, {%0,%1,%2,%3};\n"
        : "+f"(d[0]), "+f"(d[1]), "+f"(d[2]), "+f"(d[3])
        : "r"(a[0]), "r"(a[1]), "r"(a[2]), "r"(a[3]), "r"(b[0]), "r"(b[1]));
}

__device__ __forceinline__ void ldsm_x2_trans(unsigned& r0, unsigned& r1, unsigned addr)
{
    asm volatile("ldmatrix.sync.aligned.m8n8.x2.trans.shared.b16 {%0,%1}, [%2];"
        : "=r"(r0), "=r"(r1) : "r"(addr));
}

__device__ __forceinline__ void ldsm_x4(unsigned& r0, unsigned& r1, unsigned& r2,
                                        unsigned& r3, unsigned addr)
{
    asm volatile("ldmatrix.sync.aligned.m8n8.x4.shared.b16 {%0,%1,%2,%3}, [%4];"
        : "=r"(r0), "=r"(r1), "=r"(r2), "=r"(r3) : "r"(addr));
}

__device__ __forceinline__ unsigned su32(const void* p)
{
    return (unsigned)__cvta_generic_to_shared(p);
}

// bare MUFU exp2 (exp2f without fast-math is a softfloat routine)
__device__ __forceinline__ float ex2(float x)
{
    float y;
    asm("ex2.approx.ftz.f32 %0, %1;" : "=f"(y) : "f"(x));
    return y;
}

// pack value as (hi fp16) | (lo fp16 << 16); hi+lo ~ 22-bit mantissa of f
__device__ __forceinline__ unsigned int splitpack(float f)
{
    __half h = __float2half_rn(f);
    __half l = __float2half_rn(f - __half2float(h));
    return (unsigned int)__half_as_ushort(h) | ((unsigned int)__half_as_ushort(l) << 16);
}

// ---------------------------------------------------------------------------
// convert x + W0..W2 to packed split-fp16 (float4-vectorized)
__global__ __launch_bounds__(256)
void cvt_main(const float* __restrict__ x,  const float* __restrict__ W0,
              const float* __restrict__ W1, const float* __restrict__ W2)
{
    int i4 = (blockIdx.x * 256 + threadIdx.x) * 4;   // 960 blocks: XN + 3*WN
    const float* src;
    unsigned*    dst;
    if (i4 < XN) {
        src = x + i4;
        dst = g_xs + i4;
    } else {
        int o = i4 - XN;
        int r = o >> 18;          // WN = 2^18
        o &= (WN - 1);
        src = (r == 0 ? W0 : r == 1 ? W1 : W2) + o;
        dst = g_Ws[r] + o;
    }
    float4 v = *(const float4*)src;
    uint4 u;
    u.x = splitpack(v.x); u.y = splitpack(v.y);
    u.z = splitpack(v.z); u.w = splitpack(v.w);
    *(uint4*)dst = u;
}

// convert Wp (separate launch — keeps attn in the ncu-profiled slot #4)
__global__ __launch_bounds__(256)
void cvt_wp(const float* __restrict__ Wp)
{
    int i4 = (blockIdx.x * 256 + threadIdx.x) * 4;   // 256 blocks: WN
    float4 v = *(const float4*)(Wp + i4);
    uint4 u;
    u.x = splitpack(v.x); u.y = splitpack(v.y);
    u.z = splitpack(v.z); u.w = splitpack(v.w);
    *(uint4*)&g_Ws[3][i4] = u;
}

// ---------------------------------------------------------------------------
// split-fp16 GEMM core on pre-packed operands (row stride 68 = 16B-aligned rows)
__device__ __forceinline__ void gemm64_core(
    const unsigned* __restrict__ A, const unsigned* __restrict__ B,
    int row0, int col0, int kb, int ke, float (&acc)[2][2][4],
    unsigned (*sA)[68], unsigned (*sB)[68])
{
    const int tid = threadIdx.x;
    const int w  = tid >> 5, l = tid & 31;
    const int wm = w >> 2, wn = w & 3;
    const int g  = l >> 2, c2 = (l & 3) << 1;
    const int lr = tid >> 2, lc0 = (tid & 3) << 4;

    for (int kc = kb; kc < ke; kc += 64) {
        const unsigned* ap = A + (row0 + lr)*CC + kc + lc0;
        const unsigned* bp = B + (col0 + lr)*CC + kc + lc0;
        #pragma unroll
        for (int v = 0; v < 4; ++v) {
            *(uint4*)&sA[lr][lc0 + v*4] = *(const uint4*)(ap + v*4);
            *(uint4*)&sB[lr][lc0 + v*4] = *(const uint4*)(bp + v*4);
        }
        __syncthreads();
        #pragma unroll
        for (int ks = 0; ks < 4; ++ks) {
            const int k0 = ks*16 + c2;
            unsigned ahi[2][4], alo[2][4];
            #pragma unroll
            for (int mt = 0; mt < 2; ++mt) {
                const int r = wm*32 + mt*16 + g;
                uint2 p0 = *(const uint2*)&sA[r    ][k0    ];
                uint2 p1 = *(const uint2*)&sA[r + 8][k0    ];
                uint2 p2 = *(const uint2*)&sA[r    ][k0 + 8];
                uint2 p3 = *(const uint2*)&sA[r + 8][k0 + 8];
                ahi[mt][0] = __byte_perm(p0.x, p0.y, 0x5410);
                alo[mt][0] = __byte_perm(p0.x, p0.y, 0x7632);
                ahi[mt][1] = __byte_perm(p1.x, p1.y, 0x5410);
                alo[mt][1] = __byte_perm(p1.x, p1.y, 0x7632);
                ahi[mt][2] = __byte_perm(p2.x, p2.y, 0x5410);
                alo[mt][2] = __byte_perm(p2.x, p2.y, 0x7632);
                ahi[mt][3] = __byte_perm(p3.x, p3.y, 0x5410);
                alo[mt][3] = __byte_perm(p3.x, p3.y, 0x7632);
            }
            #pragma unroll
            for (int nt = 0; nt < 2; ++nt) {
                const int n = wn*16 + nt*8 + g;
                uint2 q0 = *(const uint2*)&sB[n][k0    ];
                uint2 q1 = *(const uint2*)&sB[n][k0 + 8];
                unsigned bhi[2], blo[2];
                bhi[0] = __byte_perm(q0.x, q0.y, 0x5410);
                blo[0] = __byte_perm(q0.x, q0.y, 0x7632);
                bhi[1] = __byte_perm(q1.x, q1.y, 0x5410);
                blo[1] = __byte_perm(q1.x, q1.y, 0x7632);
                #pragma unroll
                for (int mt = 0; mt < 2; ++mt) {
                    mma16816(acc[mt][nt], ahi[mt], bhi);
                    mma16816(acc[mt][nt], ahi[mt], blo);
                    mma16816(acc[mt][nt], alo[mt], bhi);
                }
            }
        }
        __syncthreads();
    }
}

// ---------------------------------------------------------------------------
// projections: q = x@W0^T, k1 = x@W1^T, k2 = x@W2^T, stored [bh][t][d]
__global__ __launch_bounds__(256)
void proj_kernel()
{
    __shared__ __align__(16) unsigned sA[64][68];
    __shared__ __align__(16) unsigned sB[64][68];
    float* dst = (blockIdx.z == 0) ? g_q : (blockIdx.z == 1) ? g_k1 : g_k2;
    const int row0 = blockIdx.y * 64, col0 = blockIdx.x * 64;
    float acc[2][2][4];
    #pragma unroll
    for (int a = 0; a < 2; ++a)
        #pragma unroll
        for (int b = 0; b < 2; ++b)
            #pragma unroll
            for (int c = 0; c < 4; ++c) acc[a][b][c] = 0.f;
    gemm64_core(g_xs, g_Ws[blockIdx.z], row0, col0, 0, CC, acc, sA, sB);

    const int w = threadIdx.x >> 5, l = threadIdx.x & 31;
    const int wm = w >> 2, wn = w & 3;
    #pragma unroll
    for (int mt = 0; mt < 2; ++mt)
        #pragma unroll
        for (int nt = 0; nt < 2; ++nt) {
            const int col = col0 + wn*16 + nt*8 + ((l & 3) << 1);
            const int h = col >> 6, d = col & 63;
            #pragma unroll
            for (int rh = 0; rh < 2; ++rh) {
                const int row = row0 + wm*32 + mt*16 + (l >> 2) + rh*8;
                const int b = row / TT, t = row - b*TT;
                float2 v = make_float2(acc[mt][nt][rh*2], acc[mt][nt][rh*2 + 1]);
                *(float2*)&dst[((b*NH + h)*TT + t)*HD + d] = v;
            }
        }
}

// ---------------------------------------------------------------------------
// one 32-token k-chunk: score MMA + ex2 + j-fold -> Qtab (local k index).
// kg0: global k base; kloc: local k base in smem/Qtab; bbase: ldmatrix addr.
template<bool MJ, bool MK>
__device__ __forceinline__ void do_chunk(
    int kg0, int kloc, int ig, int il, int j0, int g, int q2, int lane,
    unsigned bbase, const unsigned (&afr)[2][4][4], __half (*Qtab)[104],
    float& zacc)
{
    #pragma unroll
    for (int nt = 0; nt < 4; ++nt) {
        if (MJ && MK && (kg0 + nt*8) > ig) continue;  // fully-masked token group
        // B fragments via 2x ldmatrix.x4 (8 tiles: 4 ks x 2 k-halves)
        unsigned bfr[4][2];
        {
            unsigned a0 = bbase + nt*(8*144);          // +8 local token rows
            ldsm_x4(bfr[0][0], bfr[0][1], bfr[1][0], bfr[1][1], a0);
            ldsm_x4(bfr[2][0], bfr[2][1], bfr[3][0], bfr[3][1], a0 + 64);
        }
        float Qf0 = 0.f, Qf1 = 0.f;
        #pragma unroll
        for (int mt = 0; mt < 2; ++mt) {
            if (MJ && (j0 + mt*16) > ig) continue;    // whole 16-row group above i
            float acc[4] = {0.f, 0.f, 0.f, 0.f};
            #pragma unroll
            for (int ks = 0; ks < 4; ++ks) mma16816(acc, afr[mt][ks], bfr[ks]);
            const int jlo = j0 + mt*16 + g, jhi = jlo + 8;
            const int k0  = kg0 + nt*8 + q2, k1 = k0 + 1;
            bool v0 = (!MJ || jlo <= ig) && (!MK || k0 <= jlo);
            bool v1 = (!MJ || jlo <= ig) && (!MK || k1 <= jlo);
            bool v2 = (!MJ || jhi <= ig) && (!MK || k0 <= jhi);
            bool v3 = (!MJ || jhi <= ig) && (!MK || k1 <= jhi);
            float p0 = v0 ? ex2(acc[0]) : 0.f;        // scale pre-folded into q
            float p1 = v1 ? ex2(acc[1]) : 0.f;
            float p2 = v2 ? ex2(acc[2]) : 0.f;
            float p3 = v3 ? ex2(acc[3]) : 0.f;
            Qf0 += p0 + p2;
            Qf1 += p1 + p3;
        }
        // fold across the 8 j row-groups (lanes differing in bits 2..4)
        #pragma unroll
        for (int m = 4; m <= 16; m <<= 1) {
            Qf0 += __shfl_xor_sync(0xffffffffu, Qf0, m);
            Qf1 += __shfl_xor_sync(0xffffffffu, Qf1, m);
        }
        zacc += (Qf0 + Qf1) * 0.125f;                 // 8-lane replication
        unsigned qp = pkh2(Qf0, Qf1);
        if (lane < 4)                                  // lanes 0..3 cover 8 tokens
            *(unsigned*)&Qtab[il][kloc + nt*8 + (lane << 1)] = qp;
    }
}

// ---------------------------------------------------------------------------
// balanced attention: block = (bh, job); jobs capped at 3 chunks; 432 blocks.
__global__ __launch_bounds__(256, 3)
void attn_kernel()
{
    __shared__ __align__(16) __half k2s[96][72];
    __shared__ __align__(16) float  qs [32][65];
    __shared__ __align__(16) float  k1s[32][65];
    __shared__ __align__(16) __half Qtab[32][104];
    __shared__ float zred[8];

    const int bh  = blockIdx.x & 15;
    const int job = blockIdx.x >> 4;
    const int m   = c_job[job];
    const int ti  = m & 7, tj = (m >> 3) & 7;
    const int kb  = (m >> 6) & 7, ke = (m >> 9) & 7, slab = m >> 13;
    const int i0 = ti * 32, j0 = tj * 32;
    const int tid  = threadIdx.x;
    const int w    = tid >> 5, lane = tid & 31;
    const int g    = lane >> 2, q2 = (lane & 3) << 1;
    const bool diag = (ti == tj);
    const int nck  = ke - kb;            // 1..3 chunks
    const int Klocal = nck * 32;

    // ldmatrix lane base (local chunk rows)
    const unsigned bmat0 = su32(&k2s[0][0]) + (lane & 7)*144 + (lane >> 3)*16;

    // load q (prescaled) / k1 fp32 (float4); k2 rows [kb*32, ke*32) fp16; zero Qtab
    {
        const float* qg  = g_q  + (bh*TT + i0)*HD;
        const float* k1g = g_k1 + (bh*TT + j0)*HD;
        const float* k2g = g_k2 + (bh*TT + kb*32)*HD;
        for (int l = tid; l < 512; l += 256) {
            int r = l >> 4, c4 = (l & 15) << 2;
            float4 vq = *(const float4*)(qg + r*HD + c4);
            qs[r][c4]   = vq.x * QPRE; qs[r][c4+1] = vq.y * QPRE;
            qs[r][c4+2] = vq.z * QPRE; qs[r][c4+3] = vq.w * QPRE;
            float4 vk = *(const float4*)(k1g + r*HD + c4);
            k1s[r][c4]   = vk.x; k1s[r][c4+1] = vk.y;
            k1s[r][c4+2] = vk.z; k1s[r][c4+3] = vk.w;
        }
        for (int l = tid; l < Klocal*16; l += 256) {
            int r = l >> 4, c4 = (l & 15) << 2;
            float4 v2 = *(const float4*)(k2g + r*HD + c4);
            *(__half2*)&k2s[r][c4]     = __floats2half2_rn(v2.x, v2.y);
            *(__half2*)&k2s[r][c4 + 2] = __floats2half2_rn(v2.z, v2.w);
        }
        for (int l = tid; l < 1664; l += 256)          // 32 x 104 halves
            ((unsigned*)Qtab)[l] = 0u;
    }
    __syncthreads();

    float zacc = 0.f;

    for (int isub = 0; isub < 4; ++isub) {
        const int il = isub*8 + w;
        const int ig = i0 + il;

        // A fragments: W[j,d] = q[i,d]*k1[j,d] (fp16), amortized over chunks
        unsigned afr[2][4][4];
        #pragma unroll
        for (int mt = 0; mt < 2; ++mt) {
            const int jlo = mt*16 + g, jhi = jlo + 8;
            #pragma unroll
            for (int ks = 0; ks < 4; ++ks) {
                const int d0 = ks*16 + q2;
                float qa = qs[il][d0],   qb = qs[il][d0+1];
                float qc = qs[il][d0+8], qd = qs[il][d0+9];
                afr[mt][ks][0] = pkh2(qa*k1s[jlo][d0],   qb*k1s[jlo][d0+1]);
                afr[mt][ks][1] = pkh2(qa*k1s[jhi][d0],   qb*k1s[jhi][d0+1]);
                afr[mt][ks][2] = pkh2(qc*k1s[jlo][d0+8], qd*k1s[jlo][d0+9]);
                afr[mt][ks][3] = pkh2(qc*k1s[jhi][d0+8], qd*k1s[jhi][d0+9]);
            }
        }

        for (int kc = kb; kc < ke; ++kc) {
            const int kg0  = kc * 32;
            const int kloc = (kc - kb) * 32;
            const unsigned bb = bmat0 + kloc*144;
            const bool mk = (kc == tj);
            if (diag) {
                if (mk) do_chunk<true ,true >(kg0, kloc, ig, il, j0, g, q2, lane, bb, afr, Qtab, zacc);
                else    do_chunk<true ,false>(kg0, kloc, ig, il, j0, g, q2, lane, bb, afr, Qtab, zacc);
            } else {
                if (mk) do_chunk<false,true >(kg0, kloc, ig, il, j0, g, q2, lane, bb, afr, Qtab, zacc);
                else    do_chunk<false,false>(kg0, kloc, ig, il, j0, g, q2, lane, bb, afr, Qtab, zacc);
            }
        }
    }
    __syncthreads();

    // ---- PV: Np[32i, 64d] = Qtab[32i, Klocal] @ k2[Klocal, 64d] ----
    {
        const int gi = w & 1;           // i-group (16 rows)
        const int dt = w >> 1;          // d-tiles dt*8 and dt*8+32
        const int r0 = gi*16 + g;
        float pacc[2][4];
        #pragma unroll
        for (int t2 = 0; t2 < 2; ++t2)
            pacc[t2][0] = pacc[t2][1] = pacc[t2][2] = pacc[t2][3] = 0.f;

        for (int ks = 0; ks < Klocal; ks += 16) {
            unsigned afrag[4];
            afrag[0] = *(const unsigned*)&Qtab[r0    ][ks + q2];
            afrag[1] = *(const unsigned*)&Qtab[r0 + 8][ks + q2];
            afrag[2] = *(const unsigned*)&Qtab[r0    ][ks + 8 + q2];
            afrag[3] = *(const unsigned*)&Qtab[r0 + 8][ks + 8 + q2];
            #pragma unroll
            for (int t2 = 0; t2 < 2; ++t2) {
                const int d0 = dt*8 + t2*32;
                unsigned b0, b1;
                ldsm_x2_trans(b0, b1, su32(&k2s[ks + (lane & 15)][d0]));
                unsigned bfrag[2] = {b0, b1};
                mma16816(pacc[t2], afrag, bfrag);
            }
        }
        float* np = g_Np + ((slab*BH + bh)*TT + i0)*HD;
        #pragma unroll
        for (int t2 = 0; t2 < 2; ++t2) {
            const int d0 = dt*8 + t2*32 + q2;
            *(float2*)&np[(r0    )*HD + d0] = make_float2(pacc[t2][0], pacc[t2][1]);
            *(float2*)&np[(r0 + 8)*HD + d0] = make_float2(pacc[t2][2], pacc[t2][3]);
        }
    }

    // Z partial: block-reduce
    #pragma unroll
    for (int m2 = 16; m2 >= 1; m2 >>= 1)
        zacc += __shfl_xor_sync(0xffffffffu, zacc, m2);
    if (lane == 0) zred[w] = zacc;
    __syncthreads();
    if (tid == 0) {
        float z = 0.f;
        #pragma unroll
        for (int ww = 0; ww < 8; ++ww) z += zred[ww];
        g_Zp[bh*NJOB + job] = z;
    }
}

// ---------------------------------------------------------------------------
// y = (sum of valid slab partials)/Z, written PACKED split-fp16 for out GEMM
__global__ __launch_bounds__(256)
void finalize_y()
{
    __shared__ float invZ[BH];
    const int tid = threadIdx.x;
    if (tid < BH) {
        float z = 0.f;
        for (int pp = 0; pp < NJOB; ++pp) z += g_Zp[tid*NJOB + pp];
        invZ[tid] = 1.f / z;
    }
    __syncthreads();
    int e  = blockIdx.x * 256 + tid;    // < XN/4 = 49152
    int c4 = e & 127;
    int r  = e >> 7;
    int b = r / TT, t = r - b*TT;
    int h = c4 >> 4, d4 = c4 & 15;
    int bh = b*NH + h;
    float4 acc = make_float4(0.f, 0.f, 0.f, 0.f);
    const int timax = t >> 5;
    #pragma unroll
    for (int s = 0; s < NSLAB; ++s) {      // predicated -> MLP 9
        if (c_slab_tj[s] <= timax) {
            float4 v = *(const float4*)&g_Np[((s*BH + bh)*TT + t)*HD + d4*4];
            acc.x += v.x; acc.y += v.y; acc.z += v.z; acc.w += v.w;
        }
    }
    float iz = invZ[bh];
    uint4 u;
    u.x = splitpack(acc.x * iz); u.y = splitpack(acc.y * iz);
    u.z = splitpack(acc.z * iz); u.w = splitpack(acc.w * iz);
    *(uint4*)&g_ys[r*CC + c4*4] = u;
}

// ---------------------------------------------------------------------------
// out partials: K-split halves of y @ Wp^T
__global__ __launch_bounds__(256)
void out_kernel()
{
    __shared__ __align__(16) unsigned sA[64][68];
    __shared__ __align__(16) unsigned sB[64][68];
    const int row0 = blockIdx.y * 64, col0 = blockIdx.x * 64;
    const int z = blockIdx.z;
    float acc[2][2][4];
    #pragma unroll
    for (int a = 0; a < 2; ++a)
        #pragma unroll
        for (int b = 0; b < 2; ++b)
            #pragma unroll
            for (int c = 0; c < 4; ++c) acc[a][b][c] = 0.f;
    gemm64_core(g_ys, g_Ws[3], row0, col0, z*(CC/2), (z+1)*(CC/2), acc, sA, sB);

    const int w = threadIdx.x >> 5, l = threadIdx.x & 31;
    const int wm = w >> 2, wn = w & 3;
    float* op = g_outp[z];
    #pragma unroll
    for (int mt = 0; mt < 2; ++mt)
        #pragma unroll
        for (int nt = 0; nt < 2; ++nt) {
            const int col = col0 + wn*16 + nt*8 + ((l & 3) << 1);
            #pragma unroll
            for (int rh = 0; rh < 2; ++rh) {
                const int row = row0 + wm*32 + mt*16 + (l >> 2) + rh*8;
                float2 v = make_float2(acc[mt][nt][rh*2], acc[mt][nt][rh*2 + 1]);
                *(float2*)&op[row*CC + col] = v;
            }
        }
}

// ---------------------------------------------------------------------------
__global__ __launch_bounds__(256)
void reduce_out(float* __restrict__ out)
{
    int e4 = (blockIdx.x * 256 + threadIdx.x) * 4;   // < XN
    float4 a = *(const float4*)&g_outp[0][e4];
    float4 b = *(const float4*)&g_outp[1][e4];
    float4 r = make_float4(a.x + b.x, a.y + b.y, a.z + b.z, a.w + b.w);
    *(float4*)&out[e4] = r;
}

// ---------------------------------------------------------------------------
extern "C" void kernel_launch(void* const* d_in, const int* in_sizes, int n_in,
                              void* d_out, int out_size)
{
    const float* x  = (const float*)d_in[0];
    const float* W0 = (const float*)d_in[1];
    const float* W1 = (const float*)d_in[2];
    const float* W2 = (const float*)d_in[3];
    const float* Wp = (const float*)d_in[4];
    float* out = (float*)d_out;

    cvt_main<<<(XN + 3*WN)/(256*4), 256>>>(x, W0, W1, W2);     // launch 1
    cvt_wp<<<WN/(256*4), 256>>>(Wp);                            // launch 2
    dim3 pg(CC/64, (BB*TT)/64, 3);
    proj_kernel<<<pg, 256>>>();                                 // launch 3
    attn_kernel<<<NJOB*BH, 256>>>();                            // launch 4 (profiled)
    finalize_y<<<(XN/4)/256, 256>>>();
    dim3 og(CC/64, (BB*TT)/64, 2);
    out_kernel<<<og, 256>>>();
    reduce_out<<<(XN/4)/256, 256>>>(out);
}

// round 13
// speedup vs baseline: 1.4234x; 1.1613x over previous
#include <cuda_runtime.h>
#include <cuda_fp16.h>
#include <stdint.h>

#define BB 2
#define NH 8
#define TT 192
#define HD 64
#define CC 512
#define BH 16            // BB*NH
#define NTILE 6          // TT/32
#define NJOB 27          // jobs per bh (heavy (ti,tj) split at kc midpoint)
#define NSLAB 9          // (tj, kc-half) slabs
#define QPRE 0.18033688f // 0.125 * log2(e): exp(S/8) = exp2(S*QPRE)
#define XN (BB*TT*CC)    // 196608
#define WN (CC*CC)       // 262144

// job encoding: ti | tj<<3 | kb<<6 | ke<<9 | slab<<13
#define EJ(ti,tj,kb,ke,slab) ((ti)|((tj)<<3)|((kb)<<6)|((ke)<<9)|((slab)<<13))
__device__ __constant__ int c_job[NJOB] = {
    // tj=0 (1 chunk)
    EJ(0,0,0,1,0), EJ(1,0,0,1,0), EJ(2,0,0,1,0), EJ(3,0,0,1,0), EJ(4,0,0,1,0), EJ(5,0,0,1,0),
    // tj=1 (2 chunks)
    EJ(1,1,0,2,1), EJ(2,1,0,2,1), EJ(3,1,0,2,1), EJ(4,1,0,2,1), EJ(5,1,0,2,1),
    // tj=2 (3 chunks)
    EJ(2,2,0,3,2), EJ(3,2,0,3,2), EJ(4,2,0,3,2), EJ(5,2,0,3,2),
    // tj=3 split 2+2
    EJ(3,3,0,2,3), EJ(3,3,2,4,4), EJ(4,3,0,2,3), EJ(4,3,2,4,4), EJ(5,3,0,2,3), EJ(5,3,2,4,4),
    // tj=4 split 2+3
    EJ(4,4,0,2,5), EJ(4,4,2,5,6), EJ(5,4,0,2,5), EJ(5,4,2,5,6),
    // tj=5 split 3+3
    EJ(5,5,0,3,7), EJ(5,5,3,6,8)
};
__device__ __constant__ int c_slab_tj[NSLAB] = {0,1,2,3,3,4,4,5,5};

// persistent device scratch (no allocations allowed)
__device__ __align__(16) float    g_q [BH*TT*HD];
__device__ __align__(16) float    g_k1[BH*TT*HD];
__device__ __align__(16) float    g_k2[BH*TT*HD];
__device__ __align__(16) float    g_Np[NSLAB*BH*TT*HD];  // 9 slabs
__device__ __align__(16) float    g_Zp[BH*NJOB];
__device__ __align__(16) unsigned g_xs[XN];        // x packed split-fp16
__device__ __align__(16) unsigned g_Ws[4][WN];     // W0,W1,W2,Wp packed
__device__ __align__(16) unsigned g_ys[XN];        // normalized y packed
__device__ __align__(16) float    g_outp[2][XN];   // out K-split partials

// ---------------------------------------------------------------------------
// HMMA helpers
__device__ __forceinline__ unsigned int pkh2(float a, float b)
{
    __half2 h = __floats2half2_rn(a, b);
    return *reinterpret_cast<unsigned int*>(&h);
}

__device__ __forceinline__ unsigned int hmul2u(unsigned a, unsigned b)
{
    __half2 r = __hmul2(*reinterpret_cast<__half2*>(&a), *reinterpret_cast<__half2*>(&b));
    return *reinterpret_cast<unsigned int*>(&r);
}

__device__ __forceinline__ void mma16816(float* d, const unsigned int* a, const unsigned int* b)
{
    asm volatile(
        "mma.sync.aligned.m16n8k16.row.col.f32.f16.f16.f32 "
        "{%0,%1,%2,%3}, {%4,%5,%6,%7}, {%8,%9}, {%0,%1,%2,%3};\n"
        : "+f"(d[0]), "+f"(d[1]), "+f"(d[2]), "+f"(d[3])
        : "r"(a[0]), "r"(a[1]), "r"(a[2]), "r"(a[3]), "r"(b[0]), "r"(b[1]));
}

__device__ __forceinline__ void ldsm_x2_trans(unsigned& r0, unsigned& r1, unsigned addr)
{
    asm volatile("ldmatrix.sync.aligned.m8n8.x2.trans.shared.b16 {%0,%1}, [%2];"
        : "=r"(r0), "=r"(r1) : "r"(addr));
}

__device__ __forceinline__ void ldsm_x4(unsigned& r0, unsigned& r1, unsigned& r2,
                                        unsigned& r3, unsigned addr)
{
    asm volatile("ldmatrix.sync.aligned.m8n8.x4.shared.b16 {%0,%1,%2,%3}, [%4];"
        : "=r"(r0), "=r"(r1), "=r"(r2), "=r"(r3) : "r"(addr));
}

__device__ __forceinline__ unsigned su32(const void* p)
{
    return (unsigned)__cvta_generic_to_shared(p);
}

// bare MUFU exp2 (exp2f without fast-math is a softfloat routine)
__device__ __forceinline__ float ex2(float x)
{
    float y;
    asm("ex2.approx.ftz.f32 %0, %1;" : "=f"(y) : "f"(x));
    return y;
}

// pack value as (hi fp16) | (lo fp16 << 16); hi+lo ~ 22-bit mantissa of f
__device__ __forceinline__ unsigned int splitpack(float f)
{
    __half h = __float2half_rn(f);
    __half l = __float2half_rn(f - __half2float(h));
    return (unsigned int)__half_as_ushort(h) | ((unsigned int)__half_as_ushort(l) << 16);
}

// ---------------------------------------------------------------------------
// convert x + W0..W2 to packed split-fp16 (float4-vectorized)
__global__ __launch_bounds__(256)
void cvt_main(const float* __restrict__ x,  const float* __restrict__ W0,
              const float* __restrict__ W1, const float* __restrict__ W2)
{
    int i4 = (blockIdx.x * 256 + threadIdx.x) * 4;   // 960 blocks: XN + 3*WN
    const float* src;
    unsigned*    dst;
    if (i4 < XN) {
        src = x + i4;
        dst = g_xs + i4;
    } else {
        int o = i4 - XN;
        int r = o >> 18;          // WN = 2^18
        o &= (WN - 1);
        src = (r == 0 ? W0 : r == 1 ? W1 : W2) + o;
        dst = g_Ws[r] + o;
    }
    float4 v = *(const float4*)src;
    uint4 u;
    u.x = splitpack(v.x); u.y = splitpack(v.y);
    u.z = splitpack(v.z); u.w = splitpack(v.w);
    *(uint4*)dst = u;
}

// convert Wp (separate launch — keeps attn in the ncu-profiled slot #4)
__global__ __launch_bounds__(256)
void cvt_wp(const float* __restrict__ Wp)
{
    int i4 = (blockIdx.x * 256 + threadIdx.x) * 4;   // 256 blocks: WN
    float4 v = *(const float4*)(Wp + i4);
    uint4 u;
    u.x = splitpack(v.x); u.y = splitpack(v.y);
    u.z = splitpack(v.z); u.w = splitpack(v.w);
    *(uint4*)&g_Ws[3][i4] = u;
}

// ---------------------------------------------------------------------------
// split-fp16 GEMM core on pre-packed operands (row stride 68 = 16B-aligned rows)
__device__ __forceinline__ void gemm64_core(
    const unsigned* __restrict__ A, const unsigned* __restrict__ B,
    int row0, int col0, int kb, int ke, float (&acc)[2][2][4],
    unsigned (*sA)[68], unsigned (*sB)[68])
{
    const int tid = threadIdx.x;
    const int w  = tid >> 5, l = tid & 31;
    const int wm = w >> 2, wn = w & 3;
    const int g  = l >> 2, c2 = (l & 3) << 1;
    const int lr = tid >> 2, lc0 = (tid & 3) << 4;

    for (int kc = kb; kc < ke; kc += 64) {
        const unsigned* ap = A + (row0 + lr)*CC + kc + lc0;
        const unsigned* bp = B + (col0 + lr)*CC + kc + lc0;
        #pragma unroll
        for (int v = 0; v < 4; ++v) {
            *(uint4*)&sA[lr][lc0 + v*4] = *(const uint4*)(ap + v*4);
            *(uint4*)&sB[lr][lc0 + v*4] = *(const uint4*)(bp + v*4);
        }
        __syncthreads();
        #pragma unroll
        for (int ks = 0; ks < 4; ++ks) {
            const int k0 = ks*16 + c2;
            unsigned ahi[2][4], alo[2][4];
            #pragma unroll
            for (int mt = 0; mt < 2; ++mt) {
                const int r = wm*32 + mt*16 + g;
                uint2 p0 = *(const uint2*)&sA[r    ][k0    ];
                uint2 p1 = *(const uint2*)&sA[r + 8][k0    ];
                uint2 p2 = *(const uint2*)&sA[r    ][k0 + 8];
                uint2 p3 = *(const uint2*)&sA[r + 8][k0 + 8];
                ahi[mt][0] = __byte_perm(p0.x, p0.y, 0x5410);
                alo[mt][0] = __byte_perm(p0.x, p0.y, 0x7632);
                ahi[mt][1] = __byte_perm(p1.x, p1.y, 0x5410);
                alo[mt][1] = __byte_perm(p1.x, p1.y, 0x7632);
                ahi[mt][2] = __byte_perm(p2.x, p2.y, 0x5410);
                alo[mt][2] = __byte_perm(p2.x, p2.y, 0x7632);
                ahi[mt][3] = __byte_perm(p3.x, p3.y, 0x5410);
                alo[mt][3] = __byte_perm(p3.x, p3.y, 0x7632);
            }
            #pragma unroll
            for (int nt = 0; nt < 2; ++nt) {
                const int n = wn*16 + nt*8 + g;
                uint2 q0 = *(const uint2*)&sB[n][k0    ];
                uint2 q1 = *(const uint2*)&sB[n][k0 + 8];
                unsigned bhi[2], blo[2];
                bhi[0] = __byte_perm(q0.x, q0.y, 0x5410);
                blo[0] = __byte_perm(q0.x, q0.y, 0x7632);
                bhi[1] = __byte_perm(q1.x, q1.y, 0x5410);
                blo[1] = __byte_perm(q1.x, q1.y, 0x7632);
                #pragma unroll
                for (int mt = 0; mt < 2; ++mt) {
                    mma16816(acc[mt][nt], ahi[mt], bhi);
                    mma16816(acc[mt][nt], ahi[mt], blo);
                    mma16816(acc[mt][nt], alo[mt], bhi);
                }
            }
        }
        __syncthreads();
    }
}

// ---------------------------------------------------------------------------
// projections: q = x@W0^T, k1 = x@W1^T, k2 = x@W2^T, stored [bh][t][d]
__global__ __launch_bounds__(256)
void proj_kernel()
{
    __shared__ __align__(16) unsigned sA[64][68];
    __shared__ __align__(16) unsigned sB[64][68];
    float* dst = (blockIdx.z == 0) ? g_q : (blockIdx.z == 1) ? g_k1 : g_k2;
    const int row0 = blockIdx.y * 64, col0 = blockIdx.x * 64;
    float acc[2][2][4];
    #pragma unroll
    for (int a = 0; a < 2; ++a)
        #pragma unroll
        for (int b = 0; b < 2; ++b)
            #pragma unroll
            for (int c = 0; c < 4; ++c) acc[a][b][c] = 0.f;
    gemm64_core(g_xs, g_Ws[blockIdx.z], row0, col0, 0, CC, acc, sA, sB);

    const int w = threadIdx.x >> 5, l = threadIdx.x & 31;
    const int wm = w >> 2, wn = w & 3;
    #pragma unroll
    for (int mt = 0; mt < 2; ++mt)
        #pragma unroll
        for (int nt = 0; nt < 2; ++nt) {
            const int col = col0 + wn*16 + nt*8 + ((l & 3) << 1);
            const int h = col >> 6, d = col & 63;
            #pragma unroll
            for (int rh = 0; rh < 2; ++rh) {
                const int row = row0 + wm*32 + mt*16 + (l >> 2) + rh*8;
                const int b = row / TT, t = row - b*TT;
                float2 v = make_float2(acc[mt][nt][rh*2], acc[mt][nt][rh*2 + 1]);
                *(float2*)&dst[((b*NH + h)*TT + t)*HD + d] = v;
            }
        }
}

// ---------------------------------------------------------------------------
// one 32-token k-chunk: score MMA + ex2 + j-fold -> Qtab (local k index).
template<bool MJ, bool MK>
__device__ __forceinline__ void do_chunk(
    int kg0, int kloc, int ig, int il, int j0, int g, int q2, int lane,
    unsigned bbase, const unsigned (&afr)[2][4][4], __half (*Qtab)[104],
    float& zacc)
{
    #pragma unroll
    for (int nt = 0; nt < 4; ++nt) {
        if (MJ && MK && (kg0 + nt*8) > ig) continue;  // fully-masked token group
        // B fragments via 2x ldmatrix.x4 (8 tiles: 4 ks x 2 k-halves)
        unsigned bfr[4][2];
        {
            unsigned a0 = bbase + nt*(8*144);          // +8 local token rows
            ldsm_x4(bfr[0][0], bfr[0][1], bfr[1][0], bfr[1][1], a0);
            ldsm_x4(bfr[2][0], bfr[2][1], bfr[3][0], bfr[3][1], a0 + 64);
        }
        float Qf0 = 0.f, Qf1 = 0.f;
        #pragma unroll
        for (int mt = 0; mt < 2; ++mt) {
            if (MJ && (j0 + mt*16) > ig) continue;    // whole 16-row group above i
            float acc[4] = {0.f, 0.f, 0.f, 0.f};
            #pragma unroll
            for (int ks = 0; ks < 4; ++ks) mma16816(acc, afr[mt][ks], bfr[ks]);
            const int jlo = j0 + mt*16 + g, jhi = jlo + 8;
            const int k0  = kg0 + nt*8 + q2, k1 = k0 + 1;
            bool v0 = (!MJ || jlo <= ig) && (!MK || k0 <= jlo);
            bool v1 = (!MJ || jlo <= ig) && (!MK || k1 <= jlo);
            bool v2 = (!MJ || jhi <= ig) && (!MK || k0 <= jhi);
            bool v3 = (!MJ || jhi <= ig) && (!MK || k1 <= jhi);
            float p0 = v0 ? ex2(acc[0]) : 0.f;        // scale pre-folded into q
            float p1 = v1 ? ex2(acc[1]) : 0.f;
            float p2 = v2 ? ex2(acc[2]) : 0.f;
            float p3 = v3 ? ex2(acc[3]) : 0.f;
            Qf0 += p0 + p2;
            Qf1 += p1 + p3;
        }
        // fold across the 8 j row-groups (lanes differing in bits 2..4)
        #pragma unroll
        for (int m = 4; m <= 16; m <<= 1) {
            Qf0 += __shfl_xor_sync(0xffffffffu, Qf0, m);
            Qf1 += __shfl_xor_sync(0xffffffffu, Qf1, m);
        }
        zacc += (Qf0 + Qf1) * 0.125f;                 // 8-lane replication
        unsigned qp = pkh2(Qf0, Qf1);
        if (lane < 4)                                  // lanes 0..3 cover 8 tokens
            *(unsigned*)&Qtab[il][kloc + nt*8 + (lane << 1)] = qp;
    }
}

// ---------------------------------------------------------------------------
// balanced attention: block = (bh, job); jobs capped at 3 chunks; 432 blocks.
// q/k1 tiles stored PACKED half2 (stride 36 -> conflict-free fragment reads).
__global__ __launch_bounds__(256, 3)
void attn_kernel()
{
    __shared__ __align__(16) __half   k2s[96][72];
    __shared__ __align__(16) unsigned qsp[32][36];   // q pairs (prescaled)
    __shared__ __align__(16) unsigned k1p[32][36];   // k1 pairs
    __shared__ __align__(16) __half   Qtab[32][104];
    __shared__ float zred[8];

    const int bh  = blockIdx.x & 15;
    const int job = blockIdx.x >> 4;
    const int m   = c_job[job];
    const int ti  = m & 7, tj = (m >> 3) & 7;
    const int kb  = (m >> 6) & 7, ke = (m >> 9) & 7, slab = m >> 13;
    const int i0 = ti * 32, j0 = tj * 32;
    const int tid  = threadIdx.x;
    const int w    = tid >> 5, lane = tid & 31;
    const int g    = lane >> 2, q2 = (lane & 3) << 1;
    const int l4   = lane & 3;
    const bool diag = (ti == tj);
    const int nck  = ke - kb;            // 1..3 chunks
    const int Klocal = nck * 32;

    // ldmatrix lane base (local chunk rows)
    const unsigned bmat0 = su32(&k2s[0][0]) + (lane & 7)*144 + (lane >> 3)*16;

    // load q (prescaled, packed) / k1 (packed); k2 rows [kb*32, ke*32) fp16
    {
        const float* qg  = g_q  + (bh*TT + i0)*HD;
        const float* k1g = g_k1 + (bh*TT + j0)*HD;
        const float* k2g = g_k2 + (bh*TT + kb*32)*HD;
        for (int l = tid; l < 512; l += 256) {
            int r = l >> 4, p0 = (l & 15) << 1;       // pair index
            float4 vq = *(const float4*)(qg + r*HD + p0*2);
            qsp[r][p0]     = pkh2(vq.x * QPRE, vq.y * QPRE);
            qsp[r][p0 + 1] = pkh2(vq.z * QPRE, vq.w * QPRE);
            float4 vk = *(const float4*)(k1g + r*HD + p0*2);
            k1p[r][p0]     = pkh2(vk.x, vk.y);
            k1p[r][p0 + 1] = pkh2(vk.z, vk.w);
        }
        for (int l = tid; l < Klocal*16; l += 256) {
            int r = l >> 4, c4 = (l & 15) << 2;
            float4 v2 = *(const float4*)(k2g + r*HD + c4);
            *(__half2*)&k2s[r][c4]     = __floats2half2_rn(v2.x, v2.y);
            *(__half2*)&k2s[r][c4 + 2] = __floats2half2_rn(v2.z, v2.w);
        }
        for (int l = tid; l < 1664; l += 256)          // 32 x 104 halves
            ((unsigned*)Qtab)[l] = 0u;
    }
    __syncthreads();

    float zacc = 0.f;

    for (int isub = 0; isub < 4; ++isub) {
        const int il = isub*8 + w;
        const int ig = i0 + il;

        // A fragments: W[j,d] = q[i,d]*k1[j,d] via packed HMUL2
        unsigned qp0[4], qp1[4];
        #pragma unroll
        for (int ks = 0; ks < 4; ++ks) {
            qp0[ks] = qsp[il][ks*8 + l4];
            qp1[ks] = qsp[il][ks*8 + 4 + l4];
        }
        unsigned afr[2][4][4];
        #pragma unroll
        for (int mt = 0; mt < 2; ++mt) {
            const int jlo = mt*16 + g, jhi = jlo + 8;
            #pragma unroll
            for (int ks = 0; ks < 4; ++ks) {
                const int c = ks*8 + l4;
                afr[mt][ks][0] = hmul2u(qp0[ks], k1p[jlo][c]);
                afr[mt][ks][1] = hmul2u(qp0[ks], k1p[jhi][c]);
                afr[mt][ks][2] = hmul2u(qp1[ks], k1p[jlo][c + 4]);
                afr[mt][ks][3] = hmul2u(qp1[ks], k1p[jhi][c + 4]);
            }
        }

        for (int kc = kb; kc < ke; ++kc) {
            const int kg0  = kc * 32;
            const int kloc = (kc - kb) * 32;
            const unsigned bb = bmat0 + kloc*144;
            const bool mk = (kc == tj);
            if (diag) {
                if (mk) do_chunk<true ,true >(kg0, kloc, ig, il, j0, g, q2, lane, bb, afr, Qtab, zacc);
                else    do_chunk<true ,false>(kg0, kloc, ig, il, j0, g, q2, lane, bb, afr, Qtab, zacc);
            } else {
                if (mk) do_chunk<false,true >(kg0, kloc, ig, il, j0, g, q2, lane, bb, afr, Qtab, zacc);
                else    do_chunk<false,false>(kg0, kloc, ig, il, j0, g, q2, lane, bb, afr, Qtab, zacc);
            }
        }
    }
    __syncthreads();

    // ---- PV: Np[32i, 64d] = Qtab[32i, Klocal] @ k2[Klocal, 64d] ----
    {
        const int gi = w & 1;           // i-group (16 rows)
        const int dt = w >> 1;          // d-tiles dt*8 and dt*8+32
        const int r0 = gi*16 + g;
        float pacc[2][4];
        #pragma unroll
        for (int t2 = 0; t2 < 2; ++t2)
            pacc[t2][0] = pacc[t2][1] = pacc[t2][2] = pacc[t2][3] = 0.f;

        for (int ks = 0; ks < Klocal; ks += 16) {
            unsigned afrag[4];
            afrag[0] = *(const unsigned*)&Qtab[r0    ][ks + q2];
            afrag[1] = *(const unsigned*)&Qtab[r0 + 8][ks + q2];
            afrag[2] = *(const unsigned*)&Qtab[r0    ][ks + 8 + q2];
            afrag[3] = *(const unsigned*)&Qtab[r0 + 8][ks + 8 + q2];
            #pragma unroll
            for (int t2 = 0; t2 < 2; ++t2) {
                const int d0 = dt*8 + t2*32;
                unsigned b0, b1;
                ldsm_x2_trans(b0, b1, su32(&k2s[ks + (lane & 15)][d0]));
                unsigned bfrag[2] = {b0, b1};
                mma16816(pacc[t2], afrag, bfrag);
            }
        }
        float* np = g_Np + ((slab*BH + bh)*TT + i0)*HD;
        #pragma unroll
        for (int t2 = 0; t2 < 2; ++t2) {
            const int d0 = dt*8 + t2*32 + q2;
            *(float2*)&np[(r0    )*HD + d0] = make_float2(pacc[t2][0], pacc[t2][1]);
            *(float2*)&np[(r0 + 8)*HD + d0] = make_float2(pacc[t2][2], pacc[t2][3]);
        }
    }

    // Z partial: block-reduce
    #pragma unroll
    for (int m2 = 16; m2 >= 1; m2 >>= 1)
        zacc += __shfl_xor_sync(0xffffffffu, zacc, m2);
    if (lane == 0) zred[w] = zacc;
    __syncthreads();
    if (tid == 0) {
        float z = 0.f;
        #pragma unroll
        for (int ww = 0; ww < 8; ++ww) z += zred[ww];
        g_Zp[bh*NJOB + job] = z;
    }
}

// ---------------------------------------------------------------------------
// y = (sum of valid slab partials)/Z, written PACKED split-fp16 for out GEMM
__global__ __launch_bounds__(256)
void finalize_y()
{
    __shared__ float invZ[BH];
    const int tid = threadIdx.x;
    if (tid < BH) {
        float z = 0.f;
        for (int pp = 0; pp < NJOB; ++pp) z += g_Zp[tid*NJOB + pp];
        invZ[tid] = 1.f / z;
    }
    __syncthreads();
    int e  = blockIdx.x * 256 + tid;    // < XN/4 = 49152
    int c4 = e & 127;
    int r  = e >> 7;
    int b = r / TT, t = r - b*TT;
    int h = c4 >> 4, d4 = c4 & 15;
    int bh = b*NH + h;
    float4 acc = make_float4(0.f, 0.f, 0.f, 0.f);
    const int timax = t >> 5;
    #pragma unroll
    for (int s = 0; s < NSLAB; ++s) {      // predicated -> MLP 9
        if (c_slab_tj[s] <= timax) {
            float4 v = *(const float4*)&g_Np[((s*BH + bh)*TT + t)*HD + d4*4];
            acc.x += v.x; acc.y += v.y; acc.z += v.z; acc.w += v.w;
        }
    }
    float iz = invZ[bh];
    uint4 u;
    u.x = splitpack(acc.x * iz); u.y = splitpack(acc.y * iz);
    u.z = splitpack(acc.z * iz); u.w = splitpack(acc.w * iz);
    *(uint4*)&g_ys[r*CC + c4*4] = u;
}

// ---------------------------------------------------------------------------
// out partials: K-split halves of y @ Wp^T
__global__ __launch_bounds__(256)
void out_kernel()
{
    __shared__ __align__(16) unsigned sA[64][68];
    __shared__ __align__(16) unsigned sB[64][68];
    const int row0 = blockIdx.y * 64, col0 = blockIdx.x * 64;
    const int z = blockIdx.z;
    float acc[2][2][4];
    #pragma unroll
    for (int a = 0; a < 2; ++a)
        #pragma unroll
        for (int b = 0; b < 2; ++b)
            #pragma unroll
            for (int c = 0; c < 4; ++c) acc[a][b][c] = 0.f;
    gemm64_core(g_ys, g_Ws[3], row0, col0, z*(CC/2), (z+1)*(CC/2), acc, sA, sB);

    const int w = threadIdx.x >> 5, l = threadIdx.x & 31;
    const int wm = w >> 2, wn = w & 3;
    float* op = g_outp[z];
    #pragma unroll
    for (int mt = 0; mt < 2; ++mt)
        #pragma unroll
        for (int nt = 0; nt < 2; ++nt) {
            const int col = col0 + wn*16 + nt*8 + ((l & 3) << 1);
            #pragma unroll
            for (int rh = 0; rh < 2; ++rh) {
                const int row = row0 + wm*32 + mt*16 + (l >> 2) + rh*8;
                float2 v = make_float2(acc[mt][nt][rh*2], acc[mt][nt][rh*2 + 1]);
                *(float2*)&op[row*CC + col] = v;
            }
        }
}

// ---------------------------------------------------------------------------
__global__ __launch_bounds__(256)
void reduce_out(float* __restrict__ out)
{
    int e4 = (blockIdx.x * 256 + threadIdx.x) * 4;   // < XN
    float4 a = *(const float4*)&g_outp[0][e4];
    float4 b = *(const float4*)&g_outp[1][e4];
    float4 r = make_float4(a.x + b.x, a.y + b.y, a.z + b.z, a.w + b.w);
    *(float4*)&out[e4] = r;
}

// ---------------------------------------------------------------------------
extern "C" void kernel_launch(void* const* d_in, const int* in_sizes, int n_in,
                              void* d_out, int out_size)
{
    const float* x  = (const float*)d_in[0];
    const float* W0 = (const float*)d_in[1];
    const float* W1 = (const float*)d_in[2];
    const float* W2 = (const float*)d_in[3];
    const float* Wp = (const float*)d_in[4];
    float* out = (float*)d_out;

    cvt_main<<<(XN + 3*WN)/(256*4), 256>>>(x, W0, W1, W2);     // launch 1
    cvt_wp<<<WN/(256*4), 256>>>(Wp);                            // launch 2
    dim3 pg(CC/64, (BB*TT)/64, 3);
    proj_kernel<<<pg, 256>>>();                                 // launch 3
    attn_kernel<<<NJOB*BH, 256>>>();                            // launch 4 (profiled)
    finalize_y<<<(XN/4)/256, 256>>>();
    dim3 og(CC/64, (BB*TT)/64, 2);
    out_kernel<<<og, 256>>>();
    reduce_out<<<(XN/4)/256, 256>>>(out);
}

// round 15
// speedup vs baseline: 1.5216x; 1.0690x over previous
#include <cuda_runtime.h>
#include <cuda_fp16.h>
#include <stdint.h>

#define BB 2
#define NH 8
#define TT 192
#define HD 64
#define CC 512
#define BH 16            // BB*NH
#define NTILE 6          // TT/32
#define NJOB 27          // jobs per bh (heavy (ti,tj) split at kc midpoint)
#define NSLAB 9          // (tj, kc-half) slabs
#define QPRE 0.18033688f // 0.125 * log2(e): exp(S/8) = exp2(S*QPRE)
#define XN (BB*TT*CC)    // 196608
#define WN (CC*CC)       // 262144

// job encoding: ti | tj<<3 | kb<<6 | ke<<9 | slab<<13
#define EJ(ti,tj,kb,ke,slab) ((ti)|((tj)<<3)|((kb)<<6)|((ke)<<9)|((slab)<<13))
__device__ __constant__ int c_job[NJOB] = {
    // tj=0 (1 chunk)
    EJ(0,0,0,1,0), EJ(1,0,0,1,0), EJ(2,0,0,1,0), EJ(3,0,0,1,0), EJ(4,0,0,1,0), EJ(5,0,0,1,0),
    // tj=1 (2 chunks)
    EJ(1,1,0,2,1), EJ(2,1,0,2,1), EJ(3,1,0,2,1), EJ(4,1,0,2,1), EJ(5,1,0,2,1),
    // tj=2 (3 chunks)
    EJ(2,2,0,3,2), EJ(3,2,0,3,2), EJ(4,2,0,3,2), EJ(5,2,0,3,2),
    // tj=3 split 2+2
    EJ(3,3,0,2,3), EJ(3,3,2,4,4), EJ(4,3,0,2,3), EJ(4,3,2,4,4), EJ(5,3,0,2,3), EJ(5,3,2,4,4),
    // tj=4 split 2+3
    EJ(4,4,0,2,5), EJ(4,4,2,5,6), EJ(5,4,0,2,5), EJ(5,4,2,5,6),
    // tj=5 split 3+3
    EJ(5,5,0,3,7), EJ(5,5,3,6,8)
};
__device__ __constant__ int c_slab_tj[NSLAB] = {0,1,2,3,3,4,4,5,5};

// persistent device scratch (no allocations allowed)
__device__ __align__(16) float    g_q [BH*TT*HD];
__device__ __align__(16) float    g_k1[BH*TT*HD];
__device__ __align__(16) float    g_k2[BH*TT*HD];
__device__ __align__(16) float    g_Np[NSLAB*BH*TT*HD];  // 9 slabs
__device__ __align__(16) float    g_Zp[BH*NJOB];
__device__ __align__(16) unsigned g_xs[XN];        // x packed split-fp16
__device__ __align__(16) unsigned g_Ws[4][WN];     // W0,W1,W2,Wp packed
__device__ __align__(16) unsigned g_ys[XN];        // normalized y packed
__device__ __align__(16) float    g_outp[3][XN];   // out K-split partials

// ---------------------------------------------------------------------------
// HMMA helpers
__device__ __forceinline__ unsigned int pkh2(float a, float b)
{
    __half2 h = __floats2half2_rn(a, b);
    return *reinterpret_cast<unsigned int*>(&h);
}

__device__ __forceinline__ unsigned int hmul2u(unsigned a, unsigned b)
{
    __half2 r = __hmul2(*reinterpret_cast<__half2*>(&a), *reinterpret_cast<__half2*>(&b));
    return *reinterpret_cast<unsigned int*>(&r);
}

__device__ __forceinline__ void mma16816(float* d, const unsigned int* a, const unsigned int* b)
{
    asm volatile(
        "mma.sync.aligned.m16n8k16.row.col.f32.f16.f16.f32 "
        "{%0,%1,%2,%3}, {%4,%5,%6,%7}, {%8,%9}, {%0,%1,%2,%3};\n"
        : "+f"(d[0]), "+f"(d[1]), "+f"(d[2]), "+f"(d[3])
        : "r"(a[0]), "r"(a[1]), "r"(a[2]), "r"(a[3]), "r"(b[0]), "r"(b[1]));
}

__device__ __forceinline__ void ldsm_x2_trans(unsigned& r0, unsigned& r1, unsigned addr)
{
    asm volatile("ldmatrix.sync.aligned.m8n8.x2.trans.shared.b16 {%0,%1}, [%2];"
        : "=r"(r0), "=r"(r1) : "r"(addr));
}

__device__ __forceinline__ void ldsm_x4(unsigned& r0, unsigned& r1, unsigned& r2,
                                        unsigned& r3, unsigned addr)
{
    asm volatile("ldmatrix.sync.aligned.m8n8.x4.shared.b16 {%0,%1,%2,%3}, [%4];"
        : "=r"(r0), "=r"(r1), "=r"(r2), "=r"(r3) : "r"(addr));
}

__device__ __forceinline__ unsigned su32(const void* p)
{
    return (unsigned)__cvta_generic_to_shared(p);
}

// bare MUFU exp2 (exp2f without fast-math is a softfloat routine)
__device__ __forceinline__ float ex2(float x)
{
    float y;
    asm("ex2.approx.ftz.f32 %0, %1;" : "=f"(y) : "f"(x));
    return y;
}

// pack value as (hi fp16) | (lo fp16 << 16); hi+lo ~ 22-bit mantissa of f
__device__ __forceinline__ unsigned int splitpack(float f)
{
    __half h = __float2half_rn(f);
    __half l = __float2half_rn(f - __half2float(h));
    return (unsigned int)__half_as_ushort(h) | ((unsigned int)__half_as_ushort(l) << 16);
}

// ---------------------------------------------------------------------------
// convert x + W0..W2 to packed split-fp16 (float4-vectorized)
__global__ __launch_bounds__(256)
void cvt_main(const float* __restrict__ x,  const float* __restrict__ W0,
              const float* __restrict__ W1, const float* __restrict__ W2)
{
    int i4 = (blockIdx.x * 256 + threadIdx.x) * 4;   // 960 blocks: XN + 3*WN
    const float* src;
    unsigned*    dst;
    if (i4 < XN) {
        src = x + i4;
        dst = g_xs + i4;
    } else {
        int o = i4 - XN;
        int r = o >> 18;          // WN = 2^18
        o &= (WN - 1);
        src = (r == 0 ? W0 : r == 1 ? W1 : W2) + o;
        dst = g_Ws[r] + o;
    }
    float4 v = *(const float4*)src;
    uint4 u;
    u.x = splitpack(v.x); u.y = splitpack(v.y);
    u.z = splitpack(v.z); u.w = splitpack(v.w);
    *(uint4*)dst = u;
}

// convert Wp (separate launch — keeps attn in the ncu-profiled slot #4)
__global__ __launch_bounds__(256)
void cvt_wp(const float* __restrict__ Wp)
{
    int i4 = (blockIdx.x * 256 + threadIdx.x) * 4;   // 256 blocks: WN
    float4 v = *(const float4*)(Wp + i4);
    uint4 u;
    u.x = splitpack(v.x); u.y = splitpack(v.y);
    u.z = splitpack(v.z); u.w = splitpack(v.w);
    *(uint4*)&g_Ws[3][i4] = u;
}

// ---------------------------------------------------------------------------
// split-fp16 GEMM core, double-buffered: prefetch next 64x64 tiles into regs
// while computing the current tile from smem. Row stride 68 (16B-aligned).
__device__ __forceinline__ void gemm64_core(
    const unsigned* __restrict__ A, const unsigned* __restrict__ B,
    int row0, int col0, int kb, int ke, float (&acc)[2][2][4],
    unsigned (*sA)[68], unsigned (*sB)[68])
{
    const int tid = threadIdx.x;
    const int w  = tid >> 5, l = tid & 31;
    const int wm = w >> 2, wn = w & 3;
    const int g  = l >> 2, c2 = (l & 3) << 1;
    const int lr = tid >> 2, lc0 = (tid & 3) << 4;

    uint4 ra[4], rb[4];
    {
        const unsigned* ap = A + (row0 + lr)*CC + kb + lc0;
        const unsigned* bp = B + (col0 + lr)*CC + kb + lc0;
        #pragma unroll
        for (int v = 0; v < 4; ++v) {
            ra[v] = *(const uint4*)(ap + v*4);
            rb[v] = *(const uint4*)(bp + v*4);
        }
    }

    for (int kc = kb; kc < ke; kc += 64) {
        #pragma unroll
        for (int v = 0; v < 4; ++v) {
            *(uint4*)&sA[lr][lc0 + v*4] = ra[v];
            *(uint4*)&sB[lr][lc0 + v*4] = rb[v];
        }
        __syncthreads();
        if (kc + 64 < ke) {     // prefetch next tile (overlaps with compute)
            const unsigned* ap = A + (row0 + lr)*CC + kc + 64 + lc0;
            const unsigned* bp = B + (col0 + lr)*CC + kc + 64 + lc0;
            #pragma unroll
            for (int v = 0; v < 4; ++v) {
                ra[v] = *(const uint4*)(ap + v*4);
                rb[v] = *(const uint4*)(bp + v*4);
            }
        }
        #pragma unroll
        for (int ks = 0; ks < 4; ++ks) {
            const int k0 = ks*16 + c2;
            unsigned ahi[2][4], alo[2][4];
            #pragma unroll
            for (int mt = 0; mt < 2; ++mt) {
                const int r = wm*32 + mt*16 + g;
                uint2 p0 = *(const uint2*)&sA[r    ][k0    ];
                uint2 p1 = *(const uint2*)&sA[r + 8][k0    ];
                uint2 p2 = *(const uint2*)&sA[r    ][k0 + 8];
                uint2 p3 = *(const uint2*)&sA[r + 8][k0 + 8];
                ahi[mt][0] = __byte_perm(p0.x, p0.y, 0x5410);
                alo[mt][0] = __byte_perm(p0.x, p0.y, 0x7632);
                ahi[mt][1] = __byte_perm(p1.x, p1.y, 0x5410);
                alo[mt][1] = __byte_perm(p1.x, p1.y, 0x7632);
                ahi[mt][2] = __byte_perm(p2.x, p2.y, 0x5410);
                alo[mt][2] = __byte_perm(p2.x, p2.y, 0x7632);
                ahi[mt][3] = __byte_perm(p3.x, p3.y, 0x5410);
                alo[mt][3] = __byte_perm(p3.x, p3.y, 0x7632);
            }
            #pragma unroll
            for (int nt = 0; nt < 2; ++nt) {
                const int n = wn*16 + nt*8 + g;
                uint2 q0 = *(const uint2*)&sB[n][k0    ];
                uint2 q1 = *(const uint2*)&sB[n][k0 + 8];
                unsigned bhi[2], blo[2];
                bhi[0] = __byte_perm(q0.x, q0.y, 0x5410);
                blo[0] = __byte_perm(q0.x, q0.y, 0x7632);
                bhi[1] = __byte_perm(q1.x, q1.y, 0x5410);
                blo[1] = __byte_perm(q1.x, q1.y, 0x7632);
                #pragma unroll
                for (int mt = 0; mt < 2; ++mt) {
                    mma16816(acc[mt][nt], ahi[mt], bhi);
                    mma16816(acc[mt][nt], ahi[mt], blo);
                    mma16816(acc[mt][nt], alo[mt], bhi);
                }
            }
        }
        __syncthreads();
    }
}

// ---------------------------------------------------------------------------
// projections: q = x@W0^T, k1 = x@W1^T, k2 = x@W2^T, stored [bh][t][d]
__global__ __launch_bounds__(256)
void proj_kernel()
{
    __shared__ __align__(16) unsigned sA[64][68];
    __shared__ __align__(16) unsigned sB[64][68];
    float* dst = (blockIdx.z == 0) ? g_q : (blockIdx.z == 1) ? g_k1 : g_k2;
    const int row0 = blockIdx.y * 64, col0 = blockIdx.x * 64;
    float acc[2][2][4];
    #pragma unroll
    for (int a = 0; a < 2; ++a)
        #pragma unroll
        for (int b = 0; b < 2; ++b)
            #pragma unroll
            for (int c = 0; c < 4; ++c) acc[a][b][c] = 0.f;
    gemm64_core(g_xs, g_Ws[blockIdx.z], row0, col0, 0, CC, acc, sA, sB);

    const int w = threadIdx.x >> 5, l = threadIdx.x & 31;
    const int wm = w >> 2, wn = w & 3;
    #pragma unroll
    for (int mt = 0; mt < 2; ++mt)
        #pragma unroll
        for (int nt = 0; nt < 2; ++nt) {
            const int col = col0 + wn*16 + nt*8 + ((l & 3) << 1);
            const int h = col >> 6, d = col & 63;
            #pragma unroll
            for (int rh = 0; rh < 2; ++rh) {
                const int row = row0 + wm*32 + mt*16 + (l >> 2) + rh*8;
                const int b = row / TT, t = row - b*TT;
                float2 v = make_float2(acc[mt][nt][rh*2], acc[mt][nt][rh*2 + 1]);
                *(float2*)&dst[((b*NH + h)*TT + t)*HD + d] = v;
            }
        }
}

// ---------------------------------------------------------------------------
// one 32-token k-chunk: score MMA + ex2 + j-fold -> Qtab (local k index).
template<bool MJ, bool MK>
__device__ __forceinline__ void do_chunk(
    int kg0, int kloc, int ig, int il, int j0, int g, int q2, int lane,
    unsigned bbase, const unsigned (&afr)[2][4][4], __half (*Qtab)[104],
    float& zacc)
{
    #pragma unroll
    for (int nt = 0; nt < 4; ++nt) {
        if (MJ && MK && (kg0 + nt*8) > ig) continue;  // fully-masked token group
        // B fragments via 2x ldmatrix.x4 (8 tiles: 4 ks x 2 k-halves)
        unsigned bfr[4][2];
        {
            unsigned a0 = bbase + nt*(8*144);          // +8 local token rows
            ldsm_x4(bfr[0][0], bfr[0][1], bfr[1][0], bfr[1][1], a0);
            ldsm_x4(bfr[2][0], bfr[2][1], bfr[3][0], bfr[3][1], a0 + 64);
        }
        float Qf0 = 0.f, Qf1 = 0.f;
        #pragma unroll
        for (int mt = 0; mt < 2; ++mt) {
            if (MJ && (j0 + mt*16) > ig) continue;    // whole 16-row group above i
            float acc[4] = {0.f, 0.f, 0.f, 0.f};
            #pragma unroll
            for (int ks = 0; ks < 4; ++ks) mma16816(acc, afr[mt][ks], bfr[ks]);
            const int jlo = j0 + mt*16 + g, jhi = jlo + 8;
            const int k0  = kg0 + nt*8 + q2, k1 = k0 + 1;
            bool v0 = (!MJ || jlo <= ig) && (!MK || k0 <= jlo);
            bool v1 = (!MJ || jlo <= ig) && (!MK || k1 <= jlo);
            bool v2 = (!MJ || jhi <= ig) && (!MK || k0 <= jhi);
            bool v3 = (!MJ || jhi <= ig) && (!MK || k1 <= jhi);
            float p0 = v0 ? ex2(acc[0]) : 0.f;        // scale pre-folded into q
            float p1 = v1 ? ex2(acc[1]) : 0.f;
            float p2 = v2 ? ex2(acc[2]) : 0.f;
            float p3 = v3 ? ex2(acc[3]) : 0.f;
            Qf0 += p0 + p2;
            Qf1 += p1 + p3;
        }
        // fold across the 8 j row-groups (lanes differing in bits 2..4)
        #pragma unroll
        for (int m = 4; m <= 16; m <<= 1) {
            Qf0 += __shfl_xor_sync(0xffffffffu, Qf0, m);
            Qf1 += __shfl_xor_sync(0xffffffffu, Qf1, m);
        }
        zacc += (Qf0 + Qf1) * 0.125f;                 // 8-lane replication
        unsigned qp = pkh2(Qf0, Qf1);
        if (lane < 4)                                  // lanes 0..3 cover 8 tokens
            *(unsigned*)&Qtab[il][kloc + nt*8 + (lane << 1)] = qp;
    }
}

// ---------------------------------------------------------------------------
// balanced attention: block = (bh, job); jobs capped at 3 chunks; 432 blocks.
// q/k1 tiles stored PACKED half2 (stride 36 -> conflict-free fragment reads).
__global__ __launch_bounds__(256, 3)
void attn_kernel()
{
    __shared__ __align__(16) __half   k2s[96][72];
    __shared__ __align__(16) unsigned qsp[32][36];   // q pairs (prescaled)
    __shared__ __align__(16) unsigned k1p[32][36];   // k1 pairs
    __shared__ __align__(16) __half   Qtab[32][104];
    __shared__ float zred[8];

    const int bh  = blockIdx.x & 15;
    const int job = blockIdx.x >> 4;
    const int m   = c_job[job];
    const int ti  = m & 7, tj = (m >> 3) & 7;
    const int kb  = (m >> 6) & 7, ke = (m >> 9) & 7, slab = m >> 13;
    const int i0 = ti * 32, j0 = tj * 32;
    const int tid  = threadIdx.x;
    const int w    = tid >> 5, lane = tid & 31;
    const int g    = lane >> 2, q2 = (lane & 3) << 1;
    const int l4   = lane & 3;
    const bool diag = (ti == tj);
    const int nck  = ke - kb;            // 1..3 chunks
    const int Klocal = nck * 32;

    // ldmatrix lane base (local chunk rows)
    const unsigned bmat0 = su32(&k2s[0][0]) + (lane & 7)*144 + (lane >> 3)*16;

    // load q (prescaled, packed) / k1 (packed); k2 rows [kb*32, ke*32) fp16
    {
        const float* qg  = g_q  + (bh*TT + i0)*HD;
        const float* k1g = g_k1 + (bh*TT + j0)*HD;
        const float* k2g = g_k2 + (bh*TT + kb*32)*HD;
        for (int l = tid; l < 512; l += 256) {
            int r = l >> 4, p0 = (l & 15) << 1;       // pair index
            float4 vq = *(const float4*)(qg + r*HD + p0*2);
            qsp[r][p0]     = pkh2(vq.x * QPRE, vq.y * QPRE);
            qsp[r][p0 + 1] = pkh2(vq.z * QPRE, vq.w * QPRE);
            float4 vk = *(const float4*)(k1g + r*HD + p0*2);
            k1p[r][p0]     = pkh2(vk.x, vk.y);
            k1p[r][p0 + 1] = pkh2(vk.z, vk.w);
        }
        for (int l = tid; l < Klocal*16; l += 256) {
            int r = l >> 4, c4 = (l & 15) << 2;
            float4 v2 = *(const float4*)(k2g + r*HD + c4);
            *(__half2*)&k2s[r][c4]     = __floats2half2_rn(v2.x, v2.y);
            *(__half2*)&k2s[r][c4 + 2] = __floats2half2_rn(v2.z, v2.w);
        }
        for (int l = tid; l < 1664; l += 256)          // 32 x 104 halves
            ((unsigned*)Qtab)[l] = 0u;
    }
    __syncthreads();

    float zacc = 0.f;

    for (int isub = 0; isub < 4; ++isub) {
        const int il = isub*8 + w;
        const int ig = i0 + il;

        // A fragments: W[j,d] = q[i,d]*k1[j,d] via packed HMUL2
        unsigned qp0[4], qp1[4];
        #pragma unroll
        for (int ks = 0; ks < 4; ++ks) {
            qp0[ks] = qsp[il][ks*8 + l4];
            qp1[ks] = qsp[il][ks*8 + 4 + l4];
        }
        unsigned afr[2][4][4];
        #pragma unroll
        for (int mt = 0; mt < 2; ++mt) {
            const int jlo = mt*16 + g, jhi = jlo + 8;
            #pragma unroll
            for (int ks = 0; ks < 4; ++ks) {
                const int c = ks*8 + l4;
                afr[mt][ks][0] = hmul2u(qp0[ks], k1p[jlo][c]);
                afr[mt][ks][1] = hmul2u(qp0[ks], k1p[jhi][c]);
                afr[mt][ks][2] = hmul2u(qp1[ks], k1p[jlo][c + 4]);
                afr[mt][ks][3] = hmul2u(qp1[ks], k1p[jhi][c + 4]);
            }
        }

        for (int kc = kb; kc < ke; ++kc) {
            const int kg0  = kc * 32;
            const int kloc = (kc - kb) * 32;
            const unsigned bb = bmat0 + kloc*144;
            const bool mk = (kc == tj);
            if (diag) {
                if (mk) do_chunk<true ,true >(kg0, kloc, ig, il, j0, g, q2, lane, bb, afr, Qtab, zacc);
                else    do_chunk<true ,false>(kg0, kloc, ig, il, j0, g, q2, lane, bb, afr, Qtab, zacc);
            } else {
                if (mk) do_chunk<false,true >(kg0, kloc, ig, il, j0, g, q2, lane, bb, afr, Qtab, zacc);
                else    do_chunk<false,false>(kg0, kloc, ig, il, j0, g, q2, lane, bb, afr, Qtab, zacc);
            }
        }
    }
    __syncthreads();

    // ---- PV: Np[32i, 64d] = Qtab[32i, Klocal] @ k2[Klocal, 64d] ----
    {
        const int gi = w & 1;           // i-group (16 rows)
        const int dt = w >> 1;          // d-tiles dt*8 and dt*8+32
        const int r0 = gi*16 + g;
        float pacc[2][4];
        #pragma unroll
        for (int t2 = 0; t2 < 2; ++t2)
            pacc[t2][0] = pacc[t2][1] = pacc[t2][2] = pacc[t2][3] = 0.f;

        for (int ks = 0; ks < Klocal; ks += 16) {
            unsigned afrag[4];
            afrag[0] = *(const unsigned*)&Qtab[r0    ][ks + q2];
            afrag[1] = *(const unsigned*)&Qtab[r0 + 8][ks + q2];
            afrag[2] = *(const unsigned*)&Qtab[r0    ][ks + 8 + q2];
            afrag[3] = *(const unsigned*)&Qtab[r0 + 8][ks + 8 + q2];
            #pragma unroll
            for (int t2 = 0; t2 < 2; ++t2) {
                const int d0 = dt*8 + t2*32;
                unsigned b0, b1;
                ldsm_x2_trans(b0, b1, su32(&k2s[ks + (lane & 15)][d0]));
                unsigned bfrag[2] = {b0, b1};
                mma16816(pacc[t2], afrag, bfrag);
            }
        }
        float* np = g_Np + ((slab*BH + bh)*TT + i0)*HD;
        #pragma unroll
        for (int t2 = 0; t2 < 2; ++t2) {
            const int d0 = dt*8 + t2*32 + q2;
            *(float2*)&np[(r0    )*HD + d0] = make_float2(pacc[t2][0], pacc[t2][1]);
            *(float2*)&np[(r0 + 8)*HD + d0] = make_float2(pacc[t2][2], pacc[t2][3]);
        }
    }

    // Z partial: block-reduce
    #pragma unroll
    for (int m2 = 16; m2 >= 1; m2 >>= 1)
        zacc += __shfl_xor_sync(0xffffffffu, zacc, m2);
    if (lane == 0) zred[w] = zacc;
    __syncthreads();
    if (tid == 0) {
        float z = 0.f;
        #pragma unroll
        for (int ww = 0; ww < 8; ++ww) z += zred[ww];
        g_Zp[bh*NJOB + job] = z;
    }
}

// ---------------------------------------------------------------------------
// y = (sum of valid slab partials)/Z, written PACKED split-fp16 for out GEMM
__global__ __launch_bounds__(256)
void finalize_y()
{
    __shared__ float invZ[BH];
    const int tid = threadIdx.x;
    if (tid < BH) {
        float z = 0.f;
        for (int pp = 0; pp < NJOB; ++pp) z += g_Zp[tid*NJOB + pp];
        invZ[tid] = 1.f / z;
    }
    __syncthreads();
    int e  = blockIdx.x * 256 + tid;    // < XN/4 = 49152
    int c4 = e & 127;
    int r  = e >> 7;
    int b = r / TT, t = r - b*TT;
    int h = c4 >> 4, d4 = c4 & 15;
    int bh = b*NH + h;
    float4 acc = make_float4(0.f, 0.f, 0.f, 0.f);
    const int timax = t >> 5;
    #pragma unroll
    for (int s = 0; s < NSLAB; ++s) {      // predicated -> MLP 9
        if (c_slab_tj[s] <= timax) {
            float4 v = *(const float4*)&g_Np[((s*BH + bh)*TT + t)*HD + d4*4];
            acc.x += v.x; acc.y += v.y; acc.z += v.z; acc.w += v.w;
        }
    }
    float iz = invZ[bh];
    uint4 u;
    u.x = splitpack(acc.x * iz); u.y = splitpack(acc.y * iz);
    u.z = splitpack(acc.z * iz); u.w = splitpack(acc.w * iz);
    *(uint4*)&g_ys[r*CC + c4*4] = u;
}

// ---------------------------------------------------------------------------
// out partials: K-split thirds of y @ Wp^T (144 blocks = one full wave)
__global__ __launch_bounds__(256)
void out_kernel()
{
    __shared__ __align__(16) unsigned sA[64][68];
    __shared__ __align__(16) unsigned sB[64][68];
    const int row0 = blockIdx.y * 64, col0 = blockIdx.x * 64;
    const int z = blockIdx.z;
    const int kb = z * 192;
    const int ke = (z == 2) ? CC : kb + 192;
    float acc[2][2][4];
    #pragma unroll
    for (int a = 0; a < 2; ++a)
        #pragma unroll
        for (int b = 0; b < 2; ++b)
            #pragma unroll
            for (int c = 0; c < 4; ++c) acc[a][b][c] = 0.f;
    gemm64_core(g_ys, g_Ws[3], row0, col0, kb, ke, acc, sA, sB);

    const int w = threadIdx.x >> 5, l = threadIdx.x & 31;
    const int wm = w >> 2, wn = w & 3;
    float* op = g_outp[z];
    #pragma unroll
    for (int mt = 0; mt < 2; ++mt)
        #pragma unroll
        for (int nt = 0; nt < 2; ++nt) {
            const int col = col0 + wn*16 + nt*8 + ((l & 3) << 1);
            #pragma unroll
            for (int rh = 0; rh < 2; ++rh) {
                const int row = row0 + wm*32 + mt*16 + (l >> 2) + rh*8;
                float2 v = make_float2(acc[mt][nt][rh*2], acc[mt][nt][rh*2 + 1]);
                *(float2*)&op[row*CC + col] = v;
            }
        }
}

// ---------------------------------------------------------------------------
__global__ __launch_bounds__(256)
void reduce_out(float* __restrict__ out)
{
    int e4 = (blockIdx.x * 256 + threadIdx.x) * 4;   // < XN
    float4 a = *(const float4*)&g_outp[0][e4];
    float4 b = *(const float4*)&g_outp[1][e4];
    float4 c = *(const float4*)&g_outp[2][e4];
    float4 r = make_float4(a.x + b.x + c.x, a.y + b.y + c.y,
                           a.z + b.z + c.z, a.w + b.w + c.w);
    *(float4*)&out[e4] = r;
}

// ---------------------------------------------------------------------------
extern "C" void kernel_launch(void* const* d_in, const int* in_sizes, int n_in,
                              void* d_out, int out_size)
{
    const float* x  = (const float*)d_in[0];
    const float* W0 = (const float*)d_in[1];
    const float* W1 = (const float*)d_in[2];
    const float* W2 = (const float*)d_in[3];
    const float* Wp = (const float*)d_in[4];
    float* out = (float*)d_out;

    cvt_main<<<(XN + 3*WN)/(256*4), 256>>>(x, W0, W1, W2);     // launch 1
    cvt_wp<<<WN/(256*4), 256>>>(Wp);                            // launch 2
    dim3 pg(CC/64, (BB*TT)/64, 3);
    proj_kernel<<<pg, 256>>>();                                 // launch 3
    attn_kernel<<<NJOB*BH, 256>>>();                            // launch 4 (profiled)
    finalize_y<<<(XN/4)/256, 256>>>();
    dim3 og(CC/64, (BB*TT)/64, 3);
    out_kernel<<<og, 256>>>();
    reduce_out<<<(XN/4)/256, 256>>>(out);
}

// round 16
// speedup vs baseline: 1.5759x; 1.0357x over previous
#include <cuda_runtime.h>
#include <cuda_fp16.h>
#include <stdint.h>

#define BB 2
#define NH 8
#define TT 192
#define HD 64
#define CC 512
#define BH 16            // BB*NH
#define NTILE 6          // TT/32
#define NJOB 27          // jobs per bh (heavy (ti,tj) split at kc midpoint)
#define NSLAB 9          // (tj, kc-half) slabs
#define QPRE 0.18033688f // 0.125 * log2(e): exp(S/8) = exp2(S*QPRE)
#define XN (BB*TT*CC)    // 196608
#define WN (CC*CC)       // 262144

// job encoding: ti | tj<<3 | kb<<6 | ke<<9 | slab<<13
#define EJ(ti,tj,kb,ke,slab) ((ti)|((tj)<<3)|((kb)<<6)|((ke)<<9)|((slab)<<13))
__device__ __constant__ int c_job[NJOB] = {
    // tj=0 (1 chunk)
    EJ(0,0,0,1,0), EJ(1,0,0,1,0), EJ(2,0,0,1,0), EJ(3,0,0,1,0), EJ(4,0,0,1,0), EJ(5,0,0,1,0),
    // tj=1 (2 chunks)
    EJ(1,1,0,2,1), EJ(2,1,0,2,1), EJ(3,1,0,2,1), EJ(4,1,0,2,1), EJ(5,1,0,2,1),
    // tj=2 (3 chunks)
    EJ(2,2,0,3,2), EJ(3,2,0,3,2), EJ(4,2,0,3,2), EJ(5,2,0,3,2),
    // tj=3 split 2+2
    EJ(3,3,0,2,3), EJ(3,3,2,4,4), EJ(4,3,0,2,3), EJ(4,3,2,4,4), EJ(5,3,0,2,3), EJ(5,3,2,4,4),
    // tj=4 split 2+3
    EJ(4,4,0,2,5), EJ(4,4,2,5,6), EJ(5,4,0,2,5), EJ(5,4,2,5,6),
    // tj=5 split 3+3
    EJ(5,5,0,3,7), EJ(5,5,3,6,8)
};
__device__ __constant__ int c_slab_tj[NSLAB] = {0,1,2,3,3,4,4,5,5};

// persistent device scratch (no allocations allowed)
__device__ __align__(16) float    g_q [BH*TT*HD];
__device__ __align__(16) float    g_k1[BH*TT*HD];
__device__ __align__(16) float    g_k2[BH*TT*HD];
__device__ __align__(16) float    g_Np[NSLAB*BH*TT*HD];  // 9 slabs
__device__ __align__(16) float    g_Zp[BH*NJOB];
__device__ __align__(16) unsigned g_xs[XN];        // x packed split-fp16
__device__ __align__(16) unsigned g_Ws[4][WN];     // W0,W1,W2,Wp packed
__device__ __align__(16) unsigned g_ys[XN];        // normalized y packed
__device__ __align__(16) float    g_outp[3][XN];   // out K-split partials

// ---------------------------------------------------------------------------
// HMMA helpers
__device__ __forceinline__ unsigned int pkh2(float a, float b)
{
    __half2 h = __floats2half2_rn(a, b);
    return *reinterpret_cast<unsigned int*>(&h);
}

__device__ __forceinline__ unsigned int hmul2u(unsigned a, unsigned b)
{
    __half2 r = __hmul2(*reinterpret_cast<__half2*>(&a), *reinterpret_cast<__half2*>(&b));
    return *reinterpret_cast<unsigned int*>(&r);
}

__device__ __forceinline__ void mma16816(float* d, const unsigned int* a, const unsigned int* b)
{
    asm volatile(
        "mma.sync.aligned.m16n8k16.row.col.f32.f16.f16.f32 "
        "{%0,%1,%2,%3}, {%4,%5,%6,%7}, {%8,%9}, {%0,%1,%2,%3};\n"
        : "+f"(d[0]), "+f"(d[1]), "+f"(d[2]), "+f"(d[3])
        : "r"(a[0]), "r"(a[1]), "r"(a[2]), "r"(a[3]), "r"(b[0]), "r"(b[1]));
}

__device__ __forceinline__ void ldsm_x2_trans(unsigned& r0, unsigned& r1, unsigned addr)
{
    asm volatile("ldmatrix.sync.aligned.m8n8.x2.trans.shared.b16 {%0,%1}, [%2];"
        : "=r"(r0), "=r"(r1) : "r"(addr));
}

__device__ __forceinline__ void ldsm_x4(unsigned& r0, unsigned& r1, unsigned& r2,
                                        unsigned& r3, unsigned addr)
{
    asm volatile("ldmatrix.sync.aligned.m8n8.x4.shared.b16 {%0,%1,%2,%3}, [%4];"
        : "=r"(r0), "=r"(r1), "=r"(r2), "=r"(r3) : "r"(addr));
}

__device__ __forceinline__ unsigned su32(const void* p)
{
    return (unsigned)__cvta_generic_to_shared(p);
}

// bare MUFU exp2 (exp2f without fast-math is a softfloat routine)
__device__ __forceinline__ float ex2(float x)
{
    float y;
    asm("ex2.approx.ftz.f32 %0, %1;" : "=f"(y) : "f"(x));
    return y;
}

// pack value as (hi fp16) | (lo fp16 << 16); hi+lo ~ 22-bit mantissa of f
__device__ __forceinline__ unsigned int splitpack(float f)
{
    __half h = __float2half_rn(f);
    __half l = __float2half_rn(f - __half2float(h));
    return (unsigned int)__half_as_ushort(h) | ((unsigned int)__half_as_ushort(l) << 16);
}

// ---------------------------------------------------------------------------
// convert x + all four weight matrices to packed split-fp16 (float4-vectorized)
__global__ __launch_bounds__(256)
void cvt_kernel(const float* __restrict__ x,  const float* __restrict__ W0,
                const float* __restrict__ W1, const float* __restrict__ W2,
                const float* __restrict__ Wp)
{
    int i4 = (blockIdx.x * 256 + threadIdx.x) * 4;   // 1216 blocks: XN + 4*WN
    const float* src;
    unsigned*    dst;
    if (i4 < XN) {
        src = x + i4;
        dst = g_xs + i4;
    } else {
        int o = i4 - XN;
        int r = o >> 18;          // WN = 2^18
        o &= (WN - 1);
        src = (r == 0 ? W0 : r == 1 ? W1 : r == 2 ? W2 : Wp) + o;
        dst = g_Ws[r] + o;
    }
    float4 v = *(const float4*)src;
    uint4 u;
    u.x = splitpack(v.x); u.y = splitpack(v.y);
    u.z = splitpack(v.z); u.w = splitpack(v.w);
    *(uint4*)dst = u;
}

// ---------------------------------------------------------------------------
// split-fp16 GEMM core, double-buffered: prefetch next 64x64 tiles into regs
// while computing the current tile from smem. Row stride 68 (16B-aligned).
__device__ __forceinline__ void gemm64_core(
    const unsigned* __restrict__ A, const unsigned* __restrict__ B,
    int row0, int col0, int kb, int ke, float (&acc)[2][2][4],
    unsigned (*sA)[68], unsigned (*sB)[68])
{
    const int tid = threadIdx.x;
    const int w  = tid >> 5, l = tid & 31;
    const int wm = w >> 2, wn = w & 3;
    const int g  = l >> 2, c2 = (l & 3) << 1;
    const int lr = tid >> 2, lc0 = (tid & 3) << 4;

    uint4 ra[4], rb[4];
    {
        const unsigned* ap = A + (row0 + lr)*CC + kb + lc0;
        const unsigned* bp = B + (col0 + lr)*CC + kb + lc0;
        #pragma unroll
        for (int v = 0; v < 4; ++v) {
            ra[v] = *(const uint4*)(ap + v*4);
            rb[v] = *(const uint4*)(bp + v*4);
        }
    }

    for (int kc = kb; kc < ke; kc += 64) {
        #pragma unroll
        for (int v = 0; v < 4; ++v) {
            *(uint4*)&sA[lr][lc0 + v*4] = ra[v];
            *(uint4*)&sB[lr][lc0 + v*4] = rb[v];
        }
        __syncthreads();
        if (kc + 64 < ke) {     // prefetch next tile (overlaps with compute)
            const unsigned* ap = A + (row0 + lr)*CC + kc + 64 + lc0;
            const unsigned* bp = B + (col0 + lr)*CC + kc + 64 + lc0;
            #pragma unroll
            for (int v = 0; v < 4; ++v) {
                ra[v] = *(const uint4*)(ap + v*4);
                rb[v] = *(const uint4*)(bp + v*4);
            }
        }
        #pragma unroll
        for (int ks = 0; ks < 4; ++ks) {
            const int k0 = ks*16 + c2;
            unsigned ahi[2][4], alo[2][4];
            #pragma unroll
            for (int mt = 0; mt < 2; ++mt) {
                const int r = wm*32 + mt*16 + g;
                uint2 p0 = *(const uint2*)&sA[r    ][k0    ];
                uint2 p1 = *(const uint2*)&sA[r + 8][k0    ];
                uint2 p2 = *(const uint2*)&sA[r    ][k0 + 8];
                uint2 p3 = *(const uint2*)&sA[r + 8][k0 + 8];
                ahi[mt][0] = __byte_perm(p0.x, p0.y, 0x5410);
                alo[mt][0] = __byte_perm(p0.x, p0.y, 0x7632);
                ahi[mt][1] = __byte_perm(p1.x, p1.y, 0x5410);
                alo[mt][1] = __byte_perm(p1.x, p1.y, 0x7632);
                ahi[mt][2] = __byte_perm(p2.x, p2.y, 0x5410);
                alo[mt][2] = __byte_perm(p2.x, p2.y, 0x7632);
                ahi[mt][3] = __byte_perm(p3.x, p3.y, 0x5410);
                alo[mt][3] = __byte_perm(p3.x, p3.y, 0x7632);
            }
            #pragma unroll
            for (int nt = 0; nt < 2; ++nt) {
                const int n = wn*16 + nt*8 + g;
                uint2 q0 = *(const uint2*)&sB[n][k0    ];
                uint2 q1 = *(const uint2*)&sB[n][k0 + 8];
                unsigned bhi[2], blo[2];
                bhi[0] = __byte_perm(q0.x, q0.y, 0x5410);
                blo[0] = __byte_perm(q0.x, q0.y, 0x7632);
                bhi[1] = __byte_perm(q1.x, q1.y, 0x5410);
                blo[1] = __byte_perm(q1.x, q1.y, 0x7632);
                #pragma unroll
                for (int mt = 0; mt < 2; ++mt) {
                    mma16816(acc[mt][nt], ahi[mt], bhi);
                    mma16816(acc[mt][nt], ahi[mt], blo);
                    mma16816(acc[mt][nt], alo[mt], bhi);
                }
            }
        }
        __syncthreads();
    }
}

// ---------------------------------------------------------------------------
// projections: q = x@W0^T, k1 = x@W1^T, k2 = x@W2^T, stored [bh][t][d]
__global__ __launch_bounds__(256)
void proj_kernel()
{
    __shared__ __align__(16) unsigned sA[64][68];
    __shared__ __align__(16) unsigned sB[64][68];
    float* dst = (blockIdx.z == 0) ? g_q : (blockIdx.z == 1) ? g_k1 : g_k2;
    const int row0 = blockIdx.y * 64, col0 = blockIdx.x * 64;
    float acc[2][2][4];
    #pragma unroll
    for (int a = 0; a < 2; ++a)
        #pragma unroll
        for (int b = 0; b < 2; ++b)
            #pragma unroll
            for (int c = 0; c < 4; ++c) acc[a][b][c] = 0.f;
    gemm64_core(g_xs, g_Ws[blockIdx.z], row0, col0, 0, CC, acc, sA, sB);

    const int w = threadIdx.x >> 5, l = threadIdx.x & 31;
    const int wm = w >> 2, wn = w & 3;
    #pragma unroll
    for (int mt = 0; mt < 2; ++mt)
        #pragma unroll
        for (int nt = 0; nt < 2; ++nt) {
            const int col = col0 + wn*16 + nt*8 + ((l & 3) << 1);
            const int h = col >> 6, d = col & 63;
            #pragma unroll
            for (int rh = 0; rh < 2; ++rh) {
                const int row = row0 + wm*32 + mt*16 + (l >> 2) + rh*8;
                const int b = row / TT, t = row - b*TT;
                float2 v = make_float2(acc[mt][nt][rh*2], acc[mt][nt][rh*2 + 1]);
                *(float2*)&dst[((b*NH + h)*TT + t)*HD + d] = v;
            }
        }
}

// ---------------------------------------------------------------------------
// one 32-token k-chunk: score MMA + ex2 + j-fold -> Qtab (local k index).
template<bool MJ, bool MK>
__device__ __forceinline__ void do_chunk(
    int kg0, int kloc, int ig, int il, int j0, int g, int q2, int lane,
    unsigned bbase, const unsigned (&afr)[2][4][4], __half (*Qtab)[104],
    float& zacc)
{
    #pragma unroll
    for (int nt = 0; nt < 4; ++nt) {
        if (MJ && MK && (kg0 + nt*8) > ig) continue;  // fully-masked token group
        // B fragments via 2x ldmatrix.x4 (8 tiles: 4 ks x 2 k-halves)
        unsigned bfr[4][2];
        {
            unsigned a0 = bbase + nt*(8*144);          // +8 local token rows
            ldsm_x4(bfr[0][0], bfr[0][1], bfr[1][0], bfr[1][1], a0);
            ldsm_x4(bfr[2][0], bfr[2][1], bfr[3][0], bfr[3][1], a0 + 64);
        }
        float Qf0 = 0.f, Qf1 = 0.f;
        #pragma unroll
        for (int mt = 0; mt < 2; ++mt) {
            if (MJ && (j0 + mt*16) > ig) continue;    // whole 16-row group above i
            float acc[4] = {0.f, 0.f, 0.f, 0.f};
            #pragma unroll
            for (int ks = 0; ks < 4; ++ks) mma16816(acc, afr[mt][ks], bfr[ks]);
            const int jlo = j0 + mt*16 + g, jhi = jlo + 8;
            const int k0  = kg0 + nt*8 + q2, k1 = k0 + 1;
            bool v0 = (!MJ || jlo <= ig) && (!MK || k0 <= jlo);
            bool v1 = (!MJ || jlo <= ig) && (!MK || k1 <= jlo);
            bool v2 = (!MJ || jhi <= ig) && (!MK || k0 <= jhi);
            bool v3 = (!MJ || jhi <= ig) && (!MK || k1 <= jhi);
            float p0 = v0 ? ex2(acc[0]) : 0.f;        // scale pre-folded into q
            float p1 = v1 ? ex2(acc[1]) : 0.f;
            float p2 = v2 ? ex2(acc[2]) : 0.f;
            float p3 = v3 ? ex2(acc[3]) : 0.f;
            Qf0 += p0 + p2;
            Qf1 += p1 + p3;
        }
        // fold across the 8 j row-groups (lanes differing in bits 2..4)
        #pragma unroll
        for (int m = 4; m <= 16; m <<= 1) {
            Qf0 += __shfl_xor_sync(0xffffffffu, Qf0, m);
            Qf1 += __shfl_xor_sync(0xffffffffu, Qf1, m);
        }
        zacc += (Qf0 + Qf1) * 0.125f;                 // 8-lane replication
        unsigned qp = pkh2(Qf0, Qf1);
        if (lane < 4)                                  // lanes 0..3 cover 8 tokens
            *(unsigned*)&Qtab[il][kloc + nt*8 + (lane << 1)] = qp;
    }
}

// ---------------------------------------------------------------------------
// balanced attention: block = (bh, job); jobs capped at 3 chunks; 432 blocks.
// q/k1 tiles stored PACKED half2 (stride 36 -> conflict-free fragment reads).
__global__ __launch_bounds__(256, 3)
void attn_kernel()
{
    __shared__ __align__(16) __half   k2s[96][72];
    __shared__ __align__(16) unsigned qsp[32][36];   // q pairs (prescaled)
    __shared__ __align__(16) unsigned k1p[32][36];   // k1 pairs
    __shared__ __align__(16) __half   Qtab[32][104];
    __shared__ float zred[8];

    const int bh  = blockIdx.x & 15;
    const int job = blockIdx.x >> 4;
    const int m   = c_job[job];
    const int ti  = m & 7, tj = (m >> 3) & 7;
    const int kb  = (m >> 6) & 7, ke = (m >> 9) & 7, slab = m >> 13;
    const int i0 = ti * 32, j0 = tj * 32;
    const int tid  = threadIdx.x;
    const int w    = tid >> 5, lane = tid & 31;
    const int g    = lane >> 2, q2 = (lane & 3) << 1;
    const int l4   = lane & 3;
    const bool diag = (ti == tj);
    const int nck  = ke - kb;            // 1..3 chunks
    const int Klocal = nck * 32;

    // ldmatrix lane base (local chunk rows)
    const unsigned bmat0 = su32(&k2s[0][0]) + (lane & 7)*144 + (lane >> 3)*16;

    // load q (prescaled, packed) / k1 (packed); k2 rows [kb*32, ke*32) fp16
    {
        const float* qg  = g_q  + (bh*TT + i0)*HD;
        const float* k1g = g_k1 + (bh*TT + j0)*HD;
        const float* k2g = g_k2 + (bh*TT + kb*32)*HD;
        for (int l = tid; l < 512; l += 256) {
            int r = l >> 4, p0 = (l & 15) << 1;       // pair index
            float4 vq = *(const float4*)(qg + r*HD + p0*2);
            qsp[r][p0]     = pkh2(vq.x * QPRE, vq.y * QPRE);
            qsp[r][p0 + 1] = pkh2(vq.z * QPRE, vq.w * QPRE);
            float4 vk = *(const float4*)(k1g + r*HD + p0*2);
            k1p[r][p0]     = pkh2(vk.x, vk.y);
            k1p[r][p0 + 1] = pkh2(vk.z, vk.w);
        }
        for (int l = tid; l < Klocal*16; l += 256) {
            int r = l >> 4, c4 = (l & 15) << 2;
            float4 v2 = *(const float4*)(k2g + r*HD + c4);
            *(__half2*)&k2s[r][c4]     = __floats2half2_rn(v2.x, v2.y);
            *(__half2*)&k2s[r][c4 + 2] = __floats2half2_rn(v2.z, v2.w);
        }
        for (int l = tid; l < 1664; l += 256)          // 32 x 104 halves
            ((unsigned*)Qtab)[l] = 0u;
    }
    __syncthreads();

    float zacc = 0.f;

    for (int isub = 0; isub < 4; ++isub) {
        const int il = isub*8 + w;
        const int ig = i0 + il;

        // A fragments: W[j,d] = q[i,d]*k1[j,d] via packed HMUL2
        unsigned qp0[4], qp1[4];
        #pragma unroll
        for (int ks = 0; ks < 4; ++ks) {
            qp0[ks] = qsp[il][ks*8 + l4];
            qp1[ks] = qsp[il][ks*8 + 4 + l4];
        }
        unsigned afr[2][4][4];
        #pragma unroll
        for (int mt = 0; mt < 2; ++mt) {
            const int jlo = mt*16 + g, jhi = jlo + 8;
            #pragma unroll
            for (int ks = 0; ks < 4; ++ks) {
                const int c = ks*8 + l4;
                afr[mt][ks][0] = hmul2u(qp0[ks], k1p[jlo][c]);
                afr[mt][ks][1] = hmul2u(qp0[ks], k1p[jhi][c]);
                afr[mt][ks][2] = hmul2u(qp1[ks], k1p[jlo][c + 4]);
                afr[mt][ks][3] = hmul2u(qp1[ks], k1p[jhi][c + 4]);
            }
        }

        for (int kc = kb; kc < ke; ++kc) {
            const int kg0  = kc * 32;
            const int kloc = (kc - kb) * 32;
            const unsigned bb = bmat0 + kloc*144;
            const bool mk = (kc == tj);
            if (diag) {
                if (mk) do_chunk<true ,true >(kg0, kloc, ig, il, j0, g, q2, lane, bb, afr, Qtab, zacc);
                else    do_chunk<true ,false>(kg0, kloc, ig, il, j0, g, q2, lane, bb, afr, Qtab, zacc);
            } else {
                if (mk) do_chunk<false,true >(kg0, kloc, ig, il, j0, g, q2, lane, bb, afr, Qtab, zacc);
                else    do_chunk<false,false>(kg0, kloc, ig, il, j0, g, q2, lane, bb, afr, Qtab, zacc);
            }
        }
    }
    __syncthreads();

    // ---- PV: Np[32i, 64d] = Qtab[32i, Klocal] @ k2[Klocal, 64d] ----
    {
        const int gi = w & 1;           // i-group (16 rows)
        const int dt = w >> 1;          // d-tiles dt*8 and dt*8+32
        const int r0 = gi*16 + g;
        float pacc[2][4];
        #pragma unroll
        for (int t2 = 0; t2 < 2; ++t2)
            pacc[t2][0] = pacc[t2][1] = pacc[t2][2] = pacc[t2][3] = 0.f;

        for (int ks = 0; ks < Klocal; ks += 16) {
            unsigned afrag[4];
            afrag[0] = *(const unsigned*)&Qtab[r0    ][ks + q2];
            afrag[1] = *(const unsigned*)&Qtab[r0 + 8][ks + q2];
            afrag[2] = *(const unsigned*)&Qtab[r0    ][ks + 8 + q2];
            afrag[3] = *(const unsigned*)&Qtab[r0 + 8][ks + 8 + q2];
            #pragma unroll
            for (int t2 = 0; t2 < 2; ++t2) {
                const int d0 = dt*8 + t2*32;
                unsigned b0, b1;
                ldsm_x2_trans(b0, b1, su32(&k2s[ks + (lane & 15)][d0]));
                unsigned bfrag[2] = {b0, b1};
                mma16816(pacc[t2], afrag, bfrag);
            }
        }
        float* np = g_Np + ((slab*BH + bh)*TT + i0)*HD;
        #pragma unroll
        for (int t2 = 0; t2 < 2; ++t2) {
            const int d0 = dt*8 + t2*32 + q2;
            *(float2*)&np[(r0    )*HD + d0] = make_float2(pacc[t2][0], pacc[t2][1]);
            *(float2*)&np[(r0 + 8)*HD + d0] = make_float2(pacc[t2][2], pacc[t2][3]);
        }
    }

    // Z partial: block-reduce
    #pragma unroll
    for (int m2 = 16; m2 >= 1; m2 >>= 1)
        zacc += __shfl_xor_sync(0xffffffffu, zacc, m2);
    if (lane == 0) zred[w] = zacc;
    __syncthreads();
    if (tid == 0) {
        float z = 0.f;
        #pragma unroll
        for (int ww = 0; ww < 8; ++ww) z += zred[ww];
        g_Zp[bh*NJOB + job] = z;
    }
}

// ---------------------------------------------------------------------------
// y = (sum of valid slab partials)/Z, PACKED split-fp16 out. float2/thread.
__global__ __launch_bounds__(256)
void finalize_y()
{
    __shared__ float invZ[BH];
    const int tid = threadIdx.x;
    // parallel invZ: 128 threads, 8 partials per bh, shuffle-reduce
    if (tid < 128) {
        const int bh = tid >> 3, part = tid & 7;
        float z = 0.f;
        #pragma unroll
        for (int pp = part; pp < NJOB; pp += 8) z += g_Zp[bh*NJOB + pp];
        #pragma unroll
        for (int mm = 1; mm < 8; mm <<= 1)
            z += __shfl_xor_sync(0xffffffffu, z, mm);
        if (part == 0) invZ[bh] = 1.f / z;
    }
    __syncthreads();
    int e  = blockIdx.x * 256 + tid;    // < XN/2 = 98304 (384 blocks)
    int c2 = e & 255;                    // float2 index within C row
    int r  = e >> 8;
    int b = r / TT, t = r - b*TT;
    int h = c2 >> 5, d2 = c2 & 31;
    int bh = b*NH + h;
    float2 acc = make_float2(0.f, 0.f);
    const int timax = t >> 5;
    #pragma unroll
    for (int s = 0; s < NSLAB; ++s) {      // predicated -> MLP 9
        if (c_slab_tj[s] <= timax) {
            float2 v = *(const float2*)&g_Np[((s*BH + bh)*TT + t)*HD + d2*2];
            acc.x += v.x; acc.y += v.y;
        }
    }
    float iz = invZ[bh];
    uint2 u;
    u.x = splitpack(acc.x * iz);
    u.y = splitpack(acc.y * iz);
    *(uint2*)&g_ys[r*CC + c2*2] = u;
}

// ---------------------------------------------------------------------------
// out partials: K-split thirds of y @ Wp^T (144 blocks = one full wave)
__global__ __launch_bounds__(256)
void out_kernel()
{
    __shared__ __align__(16) unsigned sA[64][68];
    __shared__ __align__(16) unsigned sB[64][68];
    const int row0 = blockIdx.y * 64, col0 = blockIdx.x * 64;
    const int z = blockIdx.z;
    const int kb = z * 192;
    const int ke = (z == 2) ? CC : kb + 192;
    float acc[2][2][4];
    #pragma unroll
    for (int a = 0; a < 2; ++a)
        #pragma unroll
        for (int b = 0; b < 2; ++b)
            #pragma unroll
            for (int c = 0; c < 4; ++c) acc[a][b][c] = 0.f;
    gemm64_core(g_ys, g_Ws[3], row0, col0, kb, ke, acc, sA, sB);

    const int w = threadIdx.x >> 5, l = threadIdx.x & 31;
    const int wm = w >> 2, wn = w & 3;
    float* op = g_outp[z];
    #pragma unroll
    for (int mt = 0; mt < 2; ++mt)
        #pragma unroll
        for (int nt = 0; nt < 2; ++nt) {
            const int col = col0 + wn*16 + nt*8 + ((l & 3) << 1);
            #pragma unroll
            for (int rh = 0; rh < 2; ++rh) {
                const int row = row0 + wm*32 + mt*16 + (l >> 2) + rh*8;
                float2 v = make_float2(acc[mt][nt][rh*2], acc[mt][nt][rh*2 + 1]);
                *(float2*)&op[row*CC + col] = v;
            }
        }
}

// ---------------------------------------------------------------------------
__global__ __launch_bounds__(256)
void reduce_out(float* __restrict__ out)
{
    int e4 = (blockIdx.x * 256 + threadIdx.x) * 4;   // < XN
    float4 a = *(const float4*)&g_outp[0][e4];
    float4 b = *(const float4*)&g_outp[1][e4];
    float4 c = *(const float4*)&g_outp[2][e4];
    float4 r = make_float4(a.x + b.x + c.x, a.y + b.y + c.y,
                           a.z + b.z + c.z, a.w + b.w + c.w);
    *(float4*)&out[e4] = r;
}

// ---------------------------------------------------------------------------
extern "C" void kernel_launch(void* const* d_in, const int* in_sizes, int n_in,
                              void* d_out, int out_size)
{
    const float* x  = (const float*)d_in[0];
    const float* W0 = (const float*)d_in[1];
    const float* W1 = (const float*)d_in[2];
    const float* W2 = (const float*)d_in[3];
    const float* Wp = (const float*)d_in[4];
    float* out = (float*)d_out;

    cvt_kernel<<<(XN + 4*WN)/(256*4), 256>>>(x, W0, W1, W2, Wp);  // launch 1
    dim3 pg(CC/64, (BB*TT)/64, 3);
    proj_kernel<<<pg, 256>>>();                                    // launch 2
    attn_kernel<<<NJOB*BH, 256>>>();                               // launch 3
    finalize_y<<<(XN/2)/256, 256>>>();                             // launch 4 (profiled)
    dim3 og(CC/64, (BB*TT)/64, 3);
    out_kernel<<<og, 256>>>();                                     // launch 5
    reduce_out<<<(XN/4)/256, 256>>>(out);                          // launch 6
}